// round 7
// baseline (speedup 1.0000x reference)
#include <cuda_runtime.h>
#include <mma.h>
#include <math.h>
#include <stdint.h>

using namespace nvcuda;

// ---------------- problem constants ----------------
#define NND     25000
#define INDIM   128
#define HID     256
#define NHEADS  4
#define HEADDIM 64
#define NLAYERS 3
#define NE      500000
#define ETOT    (NE + NND)   // reference appends self-loops

// ---------------- device scratch (static, no allocation) ----------------
__device__ float g_h   [NND * HID];
__device__ float g_xl  [NND * HID];
__device__ float g_xr  [NND * HID];
__device__ float g_skip[NND * HID];
__device__ float g_tmp [NND * HID];
__device__ int   g_deg [NND];
__device__ int   g_off [NND + 1];
__device__ int   g_cur [NND];
__device__ int   g_csr [ETOT];
__device__ int   g_incl[NND];
__device__ int   g_bsum[64];
__device__ int   g_is64;

// buffer ids: 0=h 1=xl 2=xr 3=skip 4=tmp (resolved DEVICE-side only)
__device__ __forceinline__ float* buf_ptr(int id) {
    switch (id) {
        case 0: return g_h;
        case 1: return g_xl;
        case 2: return g_xr;
        case 3: return g_skip;
        default: return g_tmp;
    }
}

// edge_index declared int64 but JAX x64-disabled silently yields int32.
__global__ void detect_kernel(const void* ei) {
    if (threadIdx.x == 0 && blockIdx.x == 0) {
        const int* w = (const int*)ei;
        int nz = 0;
        #pragma unroll
        for (int k = 0; k < 64; k++) nz |= w[2 * k + 1];
        g_is64 = (nz == 0) ? 1 : 0;
    }
}

__device__ __forceinline__ int load_idx(const void* ei, long long pos) {
    if (g_is64) return (int)((const long long*)ei)[pos];
    return ((const int*)ei)[pos];
}

// ---------------- CSR construction ----------------
__global__ void zero_deg_kernel() {
    int i = blockIdx.x * blockDim.x + threadIdx.x;
    if (i < NND) g_deg[i] = 0;
}

__global__ void count_kernel(const void* __restrict__ ei) {
    int e = blockIdx.x * blockDim.x + threadIdx.x;
    if (e >= ETOT) return;
    int dst = (e < NE) ? load_idx(ei, (long long)NE + e) : (e - NE);
    atomicAdd(&g_deg[dst], 1);
}

__global__ void scan1_kernel() {   // per-block inclusive scan of degrees
    __shared__ int sh[512];
    int idx = blockIdx.x * 512 + threadIdx.x;
    int v = (idx < NND) ? g_deg[idx] : 0;
    sh[threadIdx.x] = v;
    __syncthreads();
    #pragma unroll
    for (int d = 1; d < 512; d <<= 1) {
        int t = (threadIdx.x >= d) ? sh[threadIdx.x - d] : 0;
        __syncthreads();
        sh[threadIdx.x] += t;
        __syncthreads();
    }
    if (idx < NND) g_incl[idx] = sh[threadIdx.x];
    if (threadIdx.x == 511) g_bsum[blockIdx.x] = sh[511];
}

__global__ void scan2_kernel(int nblk) {
    if (threadIdx.x == 0) {
        int run = 0;
        for (int b = 0; b < nblk; b++) {
            int s = g_bsum[b];
            g_bsum[b] = run;
            run += s;
        }
        g_off[NND] = run;
    }
}

__global__ void scan3_kernel() {
    int idx = blockIdx.x * 512 + threadIdx.x;
    if (idx < NND) {
        int e = g_incl[idx] - g_deg[idx] + g_bsum[blockIdx.x];
        g_off[idx] = e;
        g_cur[idx] = e;
    }
}

__global__ void fill_kernel(const void* __restrict__ ei) {
    int e = blockIdx.x * blockDim.x + threadIdx.x;
    if (e >= ETOT) return;
    int src, dst;
    if (e < NE) { src = load_idx(ei, e); dst = load_idx(ei, (long long)NE + e); }
    else        { src = e - NE;          dst = e - NE; }
    int pos = atomicAdd(&g_cur[dst], 1);
    g_csr[pos] = src;
}

// ---------------- 3xTF32-split tensor-core GEMM via wmma (no inline asm) ----
// C[N,256] = A[N,K] @ B[K,256];  A=Ahi+Alo (bitmask truncation, exact),
// D = Ahi*Bhi + Ahi*Blo + Alo*Bhi  (residual ~2^-24)
// Block 128x128, 8 warps, warp tile 32x64 = 2x4 wmma m16n16k8 tiles, BK=16.
// blockIdx.y: j = y>>1 selects B/C/bias, bc = y&1 selects 128-col half.

#define A_LDM 20
#define B_LDM 136

__device__ __forceinline__ float trunc_hi(float x) {
    return __uint_as_float(__float_as_uint(x) & 0xFFFFE000u);
}

template <int NB>
__global__ __launch_bounds__(256, 2)
void tf32_gemm_kernel(const float* __restrict__ Aext, int aId,
                      const float* __restrict__ B0, const float* __restrict__ B1,
                      const float* __restrict__ B2,
                      const float* __restrict__ bias0, const float* __restrict__ bias2,
                      int c0, int c1, int c2,
                      int Nrows, int K) {
    const float* A = (aId < 0) ? Aext : buf_ptr(aId);

    const int j  = blockIdx.y >> 1;
    const int bc = blockIdx.y & 1;
    const float* B = (NB == 1 || j == 0) ? B0 : ((j == 1) ? B1 : B2);
    float* C = buf_ptr((NB == 1 || j == 0) ? c0 : ((j == 1) ? c1 : c2));
    const float* bias = (NB == 1 || j == 0) ? bias0 : ((j == 2) ? bias2 : nullptr);

    __shared__ float Ahi[128][A_LDM];
    __shared__ float Alo[128][A_LDM];
    __shared__ float Bhi[16][B_LDM];
    __shared__ float Blo[16][B_LDM];
    __shared__ float sbuf[8][16][16];

    const int tid  = threadIdx.x;
    const int lane = tid & 31;
    const int wid  = tid >> 5;
    const int warp_m = wid & 3;           // 4 m-slices of 32 rows
    const int warp_n = wid >> 2;          // 2 n-slices of 64 cols

    const int br = blockIdx.x;
    const int rowBase = br * 128 + warp_m * 32;
    const int colBase = bc * 128 + warp_n * 64;

    wmma::fragment<wmma::accumulator, 16, 16, 8, float> acc[2][4];
    #pragma unroll
    for (int mt = 0; mt < 2; mt++)
        #pragma unroll
        for (int nt = 0; nt < 4; nt++)
            wmma::fill_fragment(acc[mt][nt], 0.f);

    const int arow = tid >> 2, acol = (tid & 3) * 4;   // A: 128x16
    const int bk   = tid >> 5, bn   = (tid & 31) * 4;  // B: 16x128

    for (int k0 = 0; k0 < K; k0 += 16) {
        #pragma unroll
        for (int half = 0; half < 2; half++) {
            int rl = arow + half * 64;
            int rg = br * 128 + rl;
            float4 av = make_float4(0.f, 0.f, 0.f, 0.f);
            if (rg < Nrows)
                av = *(const float4*)(A + (size_t)rg * K + k0 + acol);
            float vv[4] = {av.x, av.y, av.z, av.w};
            #pragma unroll
            for (int i = 0; i < 4; i++) {
                float hi = trunc_hi(vv[i]);
                Ahi[rl][acol + i] = hi;
                Alo[rl][acol + i] = vv[i] - hi;
            }
        }
        #pragma unroll
        for (int half = 0; half < 2; half++) {
            int kl = bk + half * 8;
            float4 bv = *(const float4*)(B + (size_t)(k0 + kl) * HID + bc * 128 + bn);
            float vv[4] = {bv.x, bv.y, bv.z, bv.w};
            #pragma unroll
            for (int i = 0; i < 4; i++) {
                float hi = trunc_hi(vv[i]);
                Bhi[kl][bn + i] = hi;
                Blo[kl][bn + i] = vv[i] - hi;
            }
        }
        __syncthreads();

        #pragma unroll
        for (int kk = 0; kk < 16; kk += 8) {
            wmma::fragment<wmma::matrix_a, 16, 16, 8, wmma::precision::tf32,
                           wmma::row_major> a_hi[2], a_lo[2];
            #pragma unroll
            for (int mt = 0; mt < 2; mt++) {
                int mr = warp_m * 32 + mt * 16;
                wmma::load_matrix_sync(a_hi[mt], &Ahi[mr][kk], A_LDM);
                wmma::load_matrix_sync(a_lo[mt], &Alo[mr][kk], A_LDM);
            }
            #pragma unroll
            for (int nt = 0; nt < 4; nt++) {
                int nc = warp_n * 64 + nt * 16;
                wmma::fragment<wmma::matrix_b, 16, 16, 8, wmma::precision::tf32,
                               wmma::row_major> b_hi, b_lo;
                wmma::load_matrix_sync(b_hi, &Bhi[kk][nc], B_LDM);
                wmma::load_matrix_sync(b_lo, &Blo[kk][nc], B_LDM);
                #pragma unroll
                for (int mt = 0; mt < 2; mt++) {
                    wmma::mma_sync(acc[mt][nt], a_hi[mt], b_hi, acc[mt][nt]);
                    wmma::mma_sync(acc[mt][nt], a_hi[mt], b_lo, acc[mt][nt]);
                    wmma::mma_sync(acc[mt][nt], a_lo[mt], b_hi, acc[mt][nt]);
                }
            }
        }
        __syncthreads();
    }

    // ---- epilogue via per-warp 16x16 staging (known layout for bias/relu)
    #pragma unroll
    for (int mt = 0; mt < 2; mt++) {
        #pragma unroll
        for (int nt = 0; nt < 4; nt++) {
            wmma::store_matrix_sync(&sbuf[wid][0][0], acc[mt][nt], 16,
                                    wmma::mem_row_major);
            __syncwarp();
            // 32 lanes x 8 elems: row = lane>>1, cols = (lane&1)*8 ..+8
            int r = lane >> 1;
            int cb = (lane & 1) * 8;
            int grow = rowBase + mt * 16 + r;
            int gcol = colBase + nt * 16 + cb;
            if (grow < Nrows) {
                float vv[8];
                #pragma unroll
                for (int i = 0; i < 8; i++) {
                    float t = sbuf[wid][r][cb + i];
                    if (bias) t = fmaxf(t + bias[gcol + i], 0.f);
                    vv[i] = t;
                }
                float4* cp = (float4*)(C + (size_t)grow * HID + gcol);
                cp[0] = make_float4(vv[0], vv[1], vv[2], vv[3]);
                cp[1] = make_float4(vv[4], vv[5], vv[6], vv[7]);
            }
            __syncwarp();
        }
    }
}

// ---------------- fused GATv2 edge aggregation + bias + skip + LN + relu ----------------
// one warp per node; lane owns channels [lane*8, lane*8+8), head = lane/8
__global__ __launch_bounds__(256)
void gat_edge_ln_kernel(const float* __restrict__ att_l,
                        const float* __restrict__ gatb_l,
                        const float* __restrict__ lng_l,
                        const float* __restrict__ lnb_l) {
    const int warp = threadIdx.x >> 5;
    const int lane = threadIdx.x & 31;
    const int i = blockIdx.x * 8 + warp;
    if (i >= NND) return;

    const int head = lane >> 3;
    const int cbase = lane * 8;

    float xr[8], attv[8];
    {
        const float4* p = (const float4*)(g_xr + (size_t)i * HID + cbase);
        float4 a = p[0], b = p[1];
        xr[0]=a.x; xr[1]=a.y; xr[2]=a.z; xr[3]=a.w;
        xr[4]=b.x; xr[5]=b.y; xr[6]=b.z; xr[7]=b.w;
        #pragma unroll
        for (int k = 0; k < 8; k++)
            attv[k] = att_l[head * HEADDIM + (lane & 7) * 8 + k];
    }

    float m = -INFINITY, s = 0.f;
    float accv[8];
    #pragma unroll
    for (int k = 0; k < 8; k++) accv[k] = 0.f;

    const int jb = g_off[i], je = g_off[i + 1];
    for (int j = jb; j < je; j++) {
        const int src = g_csr[j];
        const float4* xp = (const float4*)(g_xl + (size_t)src * HID + cbase);
        float4 a = xp[0], b = xp[1];
        float xlv[8] = {a.x, a.y, a.z, a.w, b.x, b.y, b.z, b.w};

        float partial = 0.f;
        #pragma unroll
        for (int k = 0; k < 8; k++) {
            float t = xlv[k] + xr[k];
            t = (t > 0.f) ? t : 0.2f * t;          // leaky_relu 0.2
            partial = fmaf(t, attv[k], partial);
        }
        partial += __shfl_down_sync(0xffffffffu, partial, 4);
        partial += __shfl_down_sync(0xffffffffu, partial, 2);
        partial += __shfl_down_sync(0xffffffffu, partial, 1);
        const float logit = __shfl_sync(0xffffffffu, partial, lane & ~7);

        const float nm = fmaxf(m, logit);
        const float scale = __expf(m - nm);
        const float p = __expf(logit - nm);
        s = fmaf(s, scale, p);
        m = nm;
        #pragma unroll
        for (int k = 0; k < 8; k++)
            accv[k] = fmaf(accv[k], scale, p * xlv[k]);
    }

    const float inv = 1.f / fmaxf(s, 1e-16f);

    float v[8];
    {
        const float4* sp = (const float4*)(g_skip + (size_t)i * HID + cbase);
        float4 a = sp[0], b = sp[1];
        float sk[8] = {a.x, a.y, a.z, a.w, b.x, b.y, b.z, b.w};
        #pragma unroll
        for (int k = 0; k < 8; k++)
            v[k] = accv[k] * inv + gatb_l[cbase + k] + sk[k];
    }

    float lsum = 0.f;
    #pragma unroll
    for (int k = 0; k < 8; k++) lsum += v[k];
    #pragma unroll
    for (int d = 16; d > 0; d >>= 1) lsum += __shfl_xor_sync(0xffffffffu, lsum, d);
    const float mu = lsum * (1.f / HID);

    float vsum = 0.f;
    #pragma unroll
    for (int k = 0; k < 8; k++) { float ddd = v[k] - mu; vsum = fmaf(ddd, ddd, vsum); }
    #pragma unroll
    for (int d = 16; d > 0; d >>= 1) vsum += __shfl_xor_sync(0xffffffffu, vsum, d);
    const float rstd = rsqrtf(vsum * (1.f / HID) + 1e-5f);

    float o[8];
    #pragma unroll
    for (int k = 0; k < 8; k++) {
        float t = lng_l[cbase + k] * (v[k] - mu) * rstd + lnb_l[cbase + k];
        o[k] = fmaxf(t, 0.f);
    }
    float4* hp = (float4*)(g_h + (size_t)i * HID + cbase);
    hp[0] = make_float4(o[0], o[1], o[2], o[3]);
    hp[1] = make_float4(o[4], o[5], o[6], o[7]);
}

// ---------------- output head: out[i] = dot(tmp[i,:], W2) + b2 ----------------
__global__ __launch_bounds__(256)
void out_head_kernel(const float* __restrict__ W2, const float* __restrict__ b2,
                     float* __restrict__ out) {
    const int warp = threadIdx.x >> 5;
    const int lane = threadIdx.x & 31;
    const int i = blockIdx.x * 8 + warp;
    if (i >= NND) return;

    const float4* tp = (const float4*)(g_tmp + (size_t)i * HID + lane * 8);
    const float4* wp = (const float4*)(W2 + lane * 8);
    float4 t0 = tp[0], t1 = tp[1];
    float4 w0 = wp[0], w1 = wp[1];
    float dsum = t0.x * w0.x + t0.y * w0.y + t0.z * w0.z + t0.w * w0.w
               + t1.x * w1.x + t1.y * w1.y + t1.z * w1.z + t1.w * w1.w;
    #pragma unroll
    for (int d = 16; d > 0; d >>= 1) dsum += __shfl_xor_sync(0xffffffffu, dsum, d);
    if (lane == 0) out[i] = dsum + b2[0];
}

// ---------------- launch ----------------
extern "C" void kernel_launch(void* const* d_in, const int* in_sizes, int n_in,
                              void* d_out, int out_size) {
    const float* x      = (const float*)d_in[0];
    const void*  ei     = d_in[1];                 // int32 OR int64 (device-detected)
    const float* enc_W  = (const float*)d_in[4];
    const float* enc_b  = (const float*)d_in[5];
    const float* Wl     = (const float*)d_in[6];
    const float* Wr     = (const float*)d_in[7];
    const float* att    = (const float*)d_in[8];
    const float* gat_b  = (const float*)d_in[9];
    const float* skip_W = (const float*)d_in[10];
    const float* skip_b = (const float*)d_in[11];
    const float* ln_g   = (const float*)d_in[12];
    const float* ln_b   = (const float*)d_in[13];
    const float* out_W1 = (const float*)d_in[14];
    const float* out_b1 = (const float*)d_in[15];
    const float* out_W2 = (const float*)d_in[16];
    const float* out_b2 = (const float*)d_in[17];
    float* out = (float*)d_out;

    const int NBLK_SCAN = (NND + 511) / 512;

    // CSR build
    detect_kernel<<<1, 32>>>(ei);
    zero_deg_kernel<<<(NND + 511) / 512, 512>>>();
    count_kernel<<<(ETOT + 511) / 512, 512>>>(ei);
    scan1_kernel<<<NBLK_SCAN, 512>>>();
    scan2_kernel<<<1, 32>>>(NBLK_SCAN);
    scan3_kernel<<<NBLK_SCAN, 512>>>();
    fill_kernel<<<(ETOT + 511) / 512, 512>>>(ei);

    const int NTB = (NND + 127) / 128;            // 196
    const dim3 grid1(NTB, 2);                      // single-B GEMM
    const dim3 grid3(NTB, 6);                      // triple-B GEMM

    // encoder: h = relu(x @ enc_W + enc_b)
    tf32_gemm_kernel<1><<<grid1, 256>>>(x, -1, enc_W, nullptr, nullptr,
                                        enc_b, nullptr, 0, 0, 0, NND, INDIM);

    for (int L = 0; L < NLAYERS; L++) {
        const float* WlL  = Wl + (size_t)L * HID * HID;
        const float* WrL  = Wr + (size_t)L * HID * HID;
        const float* skWL = skip_W + (size_t)L * HID * HID;

        // xl = h@Wl, xr = h@Wr, skip = relu(h@skW + skip_b) — one launch
        tf32_gemm_kernel<3><<<grid3, 256>>>(nullptr, 0, WlL, WrL, skWL,
                                            nullptr, skip_b + L * HID,
                                            1, 2, 3, NND, HID);

        gat_edge_ln_kernel<<<(NND + 7) / 8, 256>>>(
            att + L * NHEADS * HEADDIM, gat_b + L * HID,
            ln_g + L * HID, ln_b + L * HID);
    }

    // output head
    tf32_gemm_kernel<1><<<grid1, 256>>>(nullptr, 0, out_W1, nullptr, nullptr,
                                        out_b1, nullptr, 4, 4, 4, NND, HID);
    out_head_kernel<<<(NND + 7) / 8, 256>>>(out_W2, out_b2, out);

    (void)in_sizes; (void)n_in; (void)out_size;
}

// round 8
// speedup vs baseline: 1.8867x; 1.8867x over previous
#include <cuda_runtime.h>
#include <mma.h>
#include <cuda_fp16.h>
#include <math.h>
#include <stdint.h>

using namespace nvcuda;

// ---------------- problem constants ----------------
#define NND     25000
#define INDIM   128
#define HID     256
#define NHEADS  4
#define HEADDIM 64
#define NLAYERS 3
#define NE      500000
#define ETOT    (NE + NND)   // reference appends self-loops

// ---------------- device scratch (static, no allocation) ----------------
__device__ float g_h   [NND * HID];
__device__ float g_xl  [NND * HID];
__device__ float g_xr  [NND * HID];
__device__ float g_skip[NND * HID];
__device__ float g_tmp [NND * HID];
__device__ int   g_deg [NND];
__device__ int   g_off [NND + 1];
__device__ int   g_cur [NND];
__device__ int   g_csr [ETOT];
__device__ int   g_incl[NND];
__device__ int   g_bsum[64];
__device__ int   g_is64;

// buffer ids: 0=h 1=xl 2=xr 3=skip 4=tmp (resolved DEVICE-side only)
__device__ __forceinline__ float* buf_ptr(int id) {
    switch (id) {
        case 0: return g_h;
        case 1: return g_xl;
        case 2: return g_xr;
        case 3: return g_skip;
        default: return g_tmp;
    }
}

// edge_index declared int64 but JAX x64-disabled silently yields int32.
__global__ void detect_kernel(const void* ei) {
    if (threadIdx.x == 0 && blockIdx.x == 0) {
        const int* w = (const int*)ei;
        int nz = 0;
        #pragma unroll
        for (int k = 0; k < 64; k++) nz |= w[2 * k + 1];
        g_is64 = (nz == 0) ? 1 : 0;
    }
}

__device__ __forceinline__ int load_idx(const void* ei, long long pos) {
    if (g_is64) return (int)((const long long*)ei)[pos];
    return ((const int*)ei)[pos];
}

// ---------------- CSR construction ----------------
__global__ void zero_deg_kernel() {
    int i = blockIdx.x * blockDim.x + threadIdx.x;
    if (i < NND) g_deg[i] = 0;
}

__global__ void count_kernel(const void* __restrict__ ei) {
    int e = blockIdx.x * blockDim.x + threadIdx.x;
    if (e >= ETOT) return;
    int dst = (e < NE) ? load_idx(ei, (long long)NE + e) : (e - NE);
    atomicAdd(&g_deg[dst], 1);
}

__global__ void scan1_kernel() {   // per-block inclusive scan of degrees
    __shared__ int sh[512];
    int idx = blockIdx.x * 512 + threadIdx.x;
    int v = (idx < NND) ? g_deg[idx] : 0;
    sh[threadIdx.x] = v;
    __syncthreads();
    #pragma unroll
    for (int d = 1; d < 512; d <<= 1) {
        int t = (threadIdx.x >= d) ? sh[threadIdx.x - d] : 0;
        __syncthreads();
        sh[threadIdx.x] += t;
        __syncthreads();
    }
    if (idx < NND) g_incl[idx] = sh[threadIdx.x];
    if (threadIdx.x == 511) g_bsum[blockIdx.x] = sh[511];
}

__global__ void scan2_kernel(int nblk) {
    if (threadIdx.x == 0) {
        int run = 0;
        for (int b = 0; b < nblk; b++) {
            int s = g_bsum[b];
            g_bsum[b] = run;
            run += s;
        }
        g_off[NND] = run;
    }
}

__global__ void scan3_kernel() {
    int idx = blockIdx.x * 512 + threadIdx.x;
    if (idx < NND) {
        int e = g_incl[idx] - g_deg[idx] + g_bsum[blockIdx.x];
        g_off[idx] = e;
        g_cur[idx] = e;
    }
}

__global__ void fill_kernel(const void* __restrict__ ei) {
    int e = blockIdx.x * blockDim.x + threadIdx.x;
    if (e >= ETOT) return;
    int src, dst;
    if (e < NE) { src = load_idx(ei, e); dst = load_idx(ei, (long long)NE + e); }
    else        { src = e - NE;          dst = e - NE; }
    int pos = atomicAdd(&g_cur[dst], 1);
    g_csr[pos] = src;
}

// ---------------- 3xFP16-split tensor-core GEMM via wmma ----------------
// C[N,256] = A[N,K] @ B[K,256].
// fp16 has the same 11-bit mantissa as tf32: A=Ahi+Alo, B=Bhi+Blo (rn),
// D = Ahi*Bhi + Ahi*Blo + Alo*Bhi, fp32 accumulate. Residual ~2^-22.
// m16n16k16: 2x K per mma and half the smem bytes vs the tf32 version.
// Block 128x128, 8 warps, warp tile 32x64 = 2x4 wmma tiles, BK=16.
// blockIdx.y: j = y>>1 selects B/C/bias, bc = y&1 selects 128-col half.

#define A_LDM 24    // halves; 48B row stride (mult of 16B)
#define B_LDM 136   // halves; 272B row stride (mult of 16B)

template <int NB>
__global__ __launch_bounds__(256, 2)
void hsplit_gemm_kernel(const float* __restrict__ Aext, int aId,
                        const float* __restrict__ B0, const float* __restrict__ B1,
                        const float* __restrict__ B2,
                        const float* __restrict__ bias0, const float* __restrict__ bias2,
                        int c0, int c1, int c2,
                        int Nrows, int K) {
    const float* A = (aId < 0) ? Aext : buf_ptr(aId);

    const int j  = blockIdx.y >> 1;
    const int bc = blockIdx.y & 1;
    const float* B = (NB == 1 || j == 0) ? B0 : ((j == 1) ? B1 : B2);
    float* C = buf_ptr((NB == 1 || j == 0) ? c0 : ((j == 1) ? c1 : c2));
    const float* bias = (NB == 1 || j == 0) ? bias0 : ((j == 2) ? bias2 : nullptr);

    __shared__ __half Ahi[128][A_LDM];
    __shared__ __half Alo[128][A_LDM];
    __shared__ __half Bhi[16][B_LDM];
    __shared__ __half Blo[16][B_LDM];
    __shared__ float  sbuf[8][16][20];

    const int tid  = threadIdx.x;
    const int lane = tid & 31;
    const int wid  = tid >> 5;
    const int warp_m = wid & 3;           // 4 m-slices of 32 rows
    const int warp_n = wid >> 2;          // 2 n-slices of 64 cols

    const int br = blockIdx.x;
    const int rowBase = br * 128 + warp_m * 32;
    const int colBase = bc * 128 + warp_n * 64;

    wmma::fragment<wmma::accumulator, 16, 16, 16, float> acc[2][4];
    #pragma unroll
    for (int mt = 0; mt < 2; mt++)
        #pragma unroll
        for (int nt = 0; nt < 4; nt++)
            wmma::fill_fragment(acc[mt][nt], 0.f);

    // A tile 128x16: thread -> row tid>>1, 8 k-cols at (tid&1)*8
    const int arow = tid >> 1, acol = (tid & 1) * 8;
    // B tile 16x128: thread -> k tid>>4, 8 n-cols at (tid&15)*8
    const int bk = tid >> 4, bn = (tid & 15) * 8;

    for (int k0 = 0; k0 < K; k0 += 16) {
        // ---- load + split A
        {
            int rg = br * 128 + arow;
            float4 v0 = make_float4(0.f, 0.f, 0.f, 0.f);
            float4 v1 = make_float4(0.f, 0.f, 0.f, 0.f);
            if (rg < Nrows) {
                const float4* ap = (const float4*)(A + (size_t)rg * K + k0 + acol);
                v0 = ap[0]; v1 = ap[1];
            }
            float vv[8] = {v0.x, v0.y, v0.z, v0.w, v1.x, v1.y, v1.z, v1.w};
            #pragma unroll
            for (int i = 0; i < 8; i++) {
                __half hi = __float2half_rn(vv[i]);
                Ahi[arow][acol + i] = hi;
                Alo[arow][acol + i] = __float2half_rn(vv[i] - __half2float(hi));
            }
        }
        // ---- load + split B
        {
            const float4* bp = (const float4*)(B + (size_t)(k0 + bk) * HID + bc * 128 + bn);
            float4 v0 = bp[0], v1 = bp[1];
            float vv[8] = {v0.x, v0.y, v0.z, v0.w, v1.x, v1.y, v1.z, v1.w};
            #pragma unroll
            for (int i = 0; i < 8; i++) {
                __half hi = __float2half_rn(vv[i]);
                Bhi[bk][bn + i] = hi;
                Blo[bk][bn + i] = __float2half_rn(vv[i] - __half2float(hi));
            }
        }
        __syncthreads();

        wmma::fragment<wmma::matrix_a, 16, 16, 16, __half, wmma::row_major> a_hi[2], a_lo[2];
        #pragma unroll
        for (int mt = 0; mt < 2; mt++) {
            int mr = warp_m * 32 + mt * 16;
            wmma::load_matrix_sync(a_hi[mt], &Ahi[mr][0], A_LDM);
            wmma::load_matrix_sync(a_lo[mt], &Alo[mr][0], A_LDM);
        }
        #pragma unroll
        for (int nt = 0; nt < 4; nt++) {
            int nc = warp_n * 64 + nt * 16;
            wmma::fragment<wmma::matrix_b, 16, 16, 16, __half, wmma::row_major> b_hi, b_lo;
            wmma::load_matrix_sync(b_hi, &Bhi[0][nc], B_LDM);
            wmma::load_matrix_sync(b_lo, &Blo[0][nc], B_LDM);
            #pragma unroll
            for (int mt = 0; mt < 2; mt++) {
                wmma::mma_sync(acc[mt][nt], a_hi[mt], b_hi, acc[mt][nt]);
                wmma::mma_sync(acc[mt][nt], a_hi[mt], b_lo, acc[mt][nt]);
                wmma::mma_sync(acc[mt][nt], a_lo[mt], b_hi, acc[mt][nt]);
            }
        }
        __syncthreads();
    }

    // ---- epilogue via per-warp 16x20 staging (known layout for bias/relu)
    #pragma unroll
    for (int mt = 0; mt < 2; mt++) {
        #pragma unroll
        for (int nt = 0; nt < 4; nt++) {
            wmma::store_matrix_sync(&sbuf[wid][0][0], acc[mt][nt], 20,
                                    wmma::mem_row_major);
            __syncwarp();
            int r = lane >> 1;
            int cb = (lane & 1) * 8;
            int grow = rowBase + mt * 16 + r;
            int gcol = colBase + nt * 16 + cb;
            if (grow < Nrows) {
                float vv[8];
                #pragma unroll
                for (int i = 0; i < 8; i++) {
                    float t = sbuf[wid][r][cb + i];
                    if (bias) t = fmaxf(t + bias[gcol + i], 0.f);
                    vv[i] = t;
                }
                float4* cp = (float4*)(C + (size_t)grow * HID + gcol);
                cp[0] = make_float4(vv[0], vv[1], vv[2], vv[3]);
                cp[1] = make_float4(vv[4], vv[5], vv[6], vv[7]);
            }
            __syncwarp();
        }
    }
}

// ---------------- fused GATv2 edge aggregation + bias + skip + LN + relu ----------------
// one warp per node; lane owns channels [lane*8, lane*8+8), head = lane/8
__global__ __launch_bounds__(256)
void gat_edge_ln_kernel(const float* __restrict__ att_l,
                        const float* __restrict__ gatb_l,
                        const float* __restrict__ lng_l,
                        const float* __restrict__ lnb_l) {
    const int warp = threadIdx.x >> 5;
    const int lane = threadIdx.x & 31;
    const int i = blockIdx.x * 8 + warp;
    if (i >= NND) return;

    const int head = lane >> 3;
    const int cbase = lane * 8;

    float xr[8], attv[8];
    {
        const float4* p = (const float4*)(g_xr + (size_t)i * HID + cbase);
        float4 a = p[0], b = p[1];
        xr[0]=a.x; xr[1]=a.y; xr[2]=a.z; xr[3]=a.w;
        xr[4]=b.x; xr[5]=b.y; xr[6]=b.z; xr[7]=b.w;
        #pragma unroll
        for (int k = 0; k < 8; k++)
            attv[k] = att_l[head * HEADDIM + (lane & 7) * 8 + k];
    }

    float m = -INFINITY, s = 0.f;
    float accv[8];
    #pragma unroll
    for (int k = 0; k < 8; k++) accv[k] = 0.f;

    const int jb = g_off[i], je = g_off[i + 1];
    for (int j = jb; j < je; j++) {
        const int src = g_csr[j];
        const float4* xp = (const float4*)(g_xl + (size_t)src * HID + cbase);
        float4 a = xp[0], b = xp[1];
        float xlv[8] = {a.x, a.y, a.z, a.w, b.x, b.y, b.z, b.w};

        float partial = 0.f;
        #pragma unroll
        for (int k = 0; k < 8; k++) {
            float t = xlv[k] + xr[k];
            t = (t > 0.f) ? t : 0.2f * t;          // leaky_relu 0.2
            partial = fmaf(t, attv[k], partial);
        }
        partial += __shfl_down_sync(0xffffffffu, partial, 4);
        partial += __shfl_down_sync(0xffffffffu, partial, 2);
        partial += __shfl_down_sync(0xffffffffu, partial, 1);
        const float logit = __shfl_sync(0xffffffffu, partial, lane & ~7);

        const float nm = fmaxf(m, logit);
        const float scale = __expf(m - nm);
        const float p = __expf(logit - nm);
        s = fmaf(s, scale, p);
        m = nm;
        #pragma unroll
        for (int k = 0; k < 8; k++)
            accv[k] = fmaf(accv[k], scale, p * xlv[k]);
    }

    const float inv = 1.f / fmaxf(s, 1e-16f);

    float v[8];
    {
        const float4* sp = (const float4*)(g_skip + (size_t)i * HID + cbase);
        float4 a = sp[0], b = sp[1];
        float sk[8] = {a.x, a.y, a.z, a.w, b.x, b.y, b.z, b.w};
        #pragma unroll
        for (int k = 0; k < 8; k++)
            v[k] = accv[k] * inv + gatb_l[cbase + k] + sk[k];
    }

    float lsum = 0.f;
    #pragma unroll
    for (int k = 0; k < 8; k++) lsum += v[k];
    #pragma unroll
    for (int d = 16; d > 0; d >>= 1) lsum += __shfl_xor_sync(0xffffffffu, lsum, d);
    const float mu = lsum * (1.f / HID);

    float vsum = 0.f;
    #pragma unroll
    for (int k = 0; k < 8; k++) { float ddd = v[k] - mu; vsum = fmaf(ddd, ddd, vsum); }
    #pragma unroll
    for (int d = 16; d > 0; d >>= 1) vsum += __shfl_xor_sync(0xffffffffu, vsum, d);
    const float rstd = rsqrtf(vsum * (1.f / HID) + 1e-5f);

    float o[8];
    #pragma unroll
    for (int k = 0; k < 8; k++) {
        float t = lng_l[cbase + k] * (v[k] - mu) * rstd + lnb_l[cbase + k];
        o[k] = fmaxf(t, 0.f);
    }
    float4* hp = (float4*)(g_h + (size_t)i * HID + cbase);
    hp[0] = make_float4(o[0], o[1], o[2], o[3]);
    hp[1] = make_float4(o[4], o[5], o[6], o[7]);
}

// ---------------- output head: out[i] = dot(tmp[i,:], W2) + b2 ----------------
__global__ __launch_bounds__(256)
void out_head_kernel(const float* __restrict__ W2, const float* __restrict__ b2,
                     float* __restrict__ out) {
    const int warp = threadIdx.x >> 5;
    const int lane = threadIdx.x & 31;
    const int i = blockIdx.x * 8 + warp;
    if (i >= NND) return;

    const float4* tp = (const float4*)(g_tmp + (size_t)i * HID + lane * 8);
    const float4* wp = (const float4*)(W2 + lane * 8);
    float4 t0 = tp[0], t1 = tp[1];
    float4 w0 = wp[0], w1 = wp[1];
    float dsum = t0.x * w0.x + t0.y * w0.y + t0.z * w0.z + t0.w * w0.w
               + t1.x * w1.x + t1.y * w1.y + t1.z * w1.z + t1.w * w1.w;
    #pragma unroll
    for (int d = 16; d > 0; d >>= 1) dsum += __shfl_xor_sync(0xffffffffu, dsum, d);
    if (lane == 0) out[i] = dsum + b2[0];
}

// ---------------- launch ----------------
extern "C" void kernel_launch(void* const* d_in, const int* in_sizes, int n_in,
                              void* d_out, int out_size) {
    const float* x      = (const float*)d_in[0];
    const void*  ei     = d_in[1];                 // int32 OR int64 (device-detected)
    const float* enc_W  = (const float*)d_in[4];
    const float* enc_b  = (const float*)d_in[5];
    const float* Wl     = (const float*)d_in[6];
    const float* Wr     = (const float*)d_in[7];
    const float* att    = (const float*)d_in[8];
    const float* gat_b  = (const float*)d_in[9];
    const float* skip_W = (const float*)d_in[10];
    const float* skip_b = (const float*)d_in[11];
    const float* ln_g   = (const float*)d_in[12];
    const float* ln_b   = (const float*)d_in[13];
    const float* out_W1 = (const float*)d_in[14];
    const float* out_b1 = (const float*)d_in[15];
    const float* out_W2 = (const float*)d_in[16];
    const float* out_b2 = (const float*)d_in[17];
    float* out = (float*)d_out;

    const int NBLK_SCAN = (NND + 511) / 512;

    // CSR build
    detect_kernel<<<1, 32>>>(ei);
    zero_deg_kernel<<<(NND + 511) / 512, 512>>>();
    count_kernel<<<(ETOT + 511) / 512, 512>>>(ei);
    scan1_kernel<<<NBLK_SCAN, 512>>>();
    scan2_kernel<<<1, 32>>>(NBLK_SCAN);
    scan3_kernel<<<NBLK_SCAN, 512>>>();
    fill_kernel<<<(ETOT + 511) / 512, 512>>>(ei);

    const int NTB = (NND + 127) / 128;            // 196
    const dim3 grid1(NTB, 2);                      // single-B GEMM
    const dim3 grid3(NTB, 6);                      // triple-B GEMM

    // encoder: h = relu(x @ enc_W + enc_b)
    hsplit_gemm_kernel<1><<<grid1, 256>>>(x, -1, enc_W, nullptr, nullptr,
                                          enc_b, nullptr, 0, 0, 0, NND, INDIM);

    for (int L = 0; L < NLAYERS; L++) {
        const float* WlL  = Wl + (size_t)L * HID * HID;
        const float* WrL  = Wr + (size_t)L * HID * HID;
        const float* skWL = skip_W + (size_t)L * HID * HID;

        // xl = h@Wl, xr = h@Wr, skip = relu(h@skW + skip_b) — one launch
        hsplit_gemm_kernel<3><<<grid3, 256>>>(nullptr, 0, WlL, WrL, skWL,
                                              nullptr, skip_b + L * HID,
                                              1, 2, 3, NND, HID);

        gat_edge_ln_kernel<<<(NND + 7) / 8, 256>>>(
            att + L * NHEADS * HEADDIM, gat_b + L * HID,
            ln_g + L * HID, ln_b + L * HID);
    }

    // output head
    hsplit_gemm_kernel<1><<<grid1, 256>>>(nullptr, 0, out_W1, nullptr, nullptr,
                                          out_b1, nullptr, 4, 4, 4, NND, HID);
    out_head_kernel<<<(NND + 7) / 8, 256>>>(out_W2, out_b2, out);

    (void)in_sizes; (void)n_in; (void)out_size;
}

// round 10
// speedup vs baseline: 2.3097x; 1.2242x over previous
#include <cuda_runtime.h>
#include <mma.h>
#include <cuda_fp16.h>
#include <math.h>
#include <stdint.h>

using namespace nvcuda;

// ---------------- problem constants ----------------
#define NND     25000
#define INDIM   128
#define HID     256
#define NHEADS  4
#define HEADDIM 64
#define NLAYERS 3
#define NE      500000
#define ETOT    (NE + NND)   // reference appends self-loops

// packed weight-split layout (element offsets)
#define WOFF_ENC  0
#define WOFF_WL   32768
#define WOFF_WR   229376
#define WOFF_SK   425984
#define WOFF_OUT  622592
#define WTOT      688128

// ---------------- device scratch (static, no allocation) ----------------
__device__ float  g_xl  [NND * HID];
__device__ float  g_xr  [NND * HID];
__device__ float  g_skip[NND * HID];
__device__ float  g_tmp [NND * HID];
__device__ __half g_hh  [NND * HID];   // h hi-halves
__device__ __half g_hl  [NND * HID];   // h lo-halves
__device__ __half g_exh [NND * INDIM]; // x hi
__device__ __half g_exl [NND * INDIM]; // x lo
__device__ __half g_wh  [WTOT];        // weights hi
__device__ __half g_wl  [WTOT];        // weights lo
__device__ int    g_deg [NND];
__device__ int    g_off [NND + 1];
__device__ int    g_cur [NND];
__device__ int    g_csr [ETOT];
__device__ int    g_incl[NND];
__device__ int    g_bsum[64];
__device__ int    g_is64;

// float scratch ids: 1=xl 2=xr 3=skip 4=tmp
__device__ __forceinline__ float* fbuf_ptr(int id) {
    switch (id) {
        case 1: return g_xl;
        case 2: return g_xr;
        case 3: return g_skip;
        default: return g_tmp;
    }
}

// edge_index declared int64 but JAX x64-disabled silently yields int32.
__global__ void detect_kernel(const void* ei) {
    if (threadIdx.x == 0 && blockIdx.x == 0) {
        const int* w = (const int*)ei;
        int nz = 0;
        #pragma unroll
        for (int k = 0; k < 64; k++) nz |= w[2 * k + 1];
        g_is64 = (nz == 0) ? 1 : 0;
    }
}

__device__ __forceinline__ int load_idx(const void* ei, long long pos) {
    if (g_is64) return (int)((const long long*)ei)[pos];
    return ((const int*)ei)[pos];
}

// ---------------- hi/lo split helpers ----------------
__global__ void split_w_kernel(const float* __restrict__ src, int dstOff, int count) {
    int i = blockIdx.x * blockDim.x + threadIdx.x;
    if (i < count) {
        float v = src[i];
        __half hi = __float2half_rn(v);
        g_wh[dstOff + i] = hi;
        g_wl[dstOff + i] = __float2half_rn(v - __half2float(hi));
    }
}

__global__ void split_x_kernel(const float* __restrict__ src) {
    int i = blockIdx.x * blockDim.x + threadIdx.x;
    if (i < NND * INDIM) {
        float v = src[i];
        __half hi = __float2half_rn(v);
        g_exh[i] = hi;
        g_exl[i] = __float2half_rn(v - __half2float(hi));
    }
}

// ---------------- CSR construction ----------------
__global__ void zero_deg_kernel() {
    int i = blockIdx.x * blockDim.x + threadIdx.x;
    if (i < NND) g_deg[i] = 0;
}

__global__ void count_kernel(const void* __restrict__ ei) {
    int e = blockIdx.x * blockDim.x + threadIdx.x;
    if (e >= ETOT) return;
    int dst = (e < NE) ? load_idx(ei, (long long)NE + e) : (e - NE);
    atomicAdd(&g_deg[dst], 1);
}

__global__ void scan1_kernel() {
    __shared__ int sh[512];
    int idx = blockIdx.x * 512 + threadIdx.x;
    int v = (idx < NND) ? g_deg[idx] : 0;
    sh[threadIdx.x] = v;
    __syncthreads();
    #pragma unroll
    for (int d = 1; d < 512; d <<= 1) {
        int t = (threadIdx.x >= d) ? sh[threadIdx.x - d] : 0;
        __syncthreads();
        sh[threadIdx.x] += t;
        __syncthreads();
    }
    if (idx < NND) g_incl[idx] = sh[threadIdx.x];
    if (threadIdx.x == 511) g_bsum[blockIdx.x] = sh[511];
}

__global__ void scan2_kernel(int nblk) {
    if (threadIdx.x == 0) {
        int run = 0;
        for (int b = 0; b < nblk; b++) {
            int s = g_bsum[b];
            g_bsum[b] = run;
            run += s;
        }
        g_off[NND] = run;
    }
}

__global__ void scan3_kernel() {
    int idx = blockIdx.x * 512 + threadIdx.x;
    if (idx < NND) {
        int e = g_incl[idx] - g_deg[idx] + g_bsum[blockIdx.x];
        g_off[idx] = e;
        g_cur[idx] = e;
    }
}

__global__ void fill_kernel(const void* __restrict__ ei) {
    int e = blockIdx.x * blockDim.x + threadIdx.x;
    if (e >= ETOT) return;
    int src, dst;
    if (e < NE) { src = load_idx(ei, e); dst = load_idx(ei, (long long)NE + e); }
    else        { src = e - NE;          dst = e - NE; }
    int pos = atomicAdd(&g_cur[dst], 1);
    g_csr[pos] = src;
}

// ---------------- 3xFP16-split tensor-core GEMM (pre-split operands) -------
// C[N,256] = A[N,K] @ B[K,256], A/B already split in half hi/lo arrays.
// D = Ahi*Bhi + Ahi*Blo + Alo*Bhi, fp32 accumulate (residual ~2^-22).
// Block 128x128, 8 warps, warp tile 32x64 = 2x4 wmma m16n16k16, BK=16.
// blockIdx.y: j = y>>1 selects B/C/bias, bc = y&1 selects 128-col half.
// WRITEH=1: epilogue (bias+relu) written as hi/lo halves into g_hh/g_hl.

#define A_LDM 24    // halves; 48B row stride
#define B_LDM 136   // halves; 272B row stride

template <int NB, int WRITEH>
__global__ __launch_bounds__(256, 2)
void hgemm_kernel(int aId,                       // 0: g_hh/g_hl (K=256), 1: g_exh/g_exl (K=128)
                  int bOff0, int bOff1, int bOff2,
                  const float* __restrict__ bias0, const float* __restrict__ bias2,
                  int c0, int c1, int c2,
                  int Nrows, int K) {
    const __half* Ah = aId ? g_exh : g_hh;
    const __half* Al = aId ? g_exl : g_hl;

    const int j  = blockIdx.y >> 1;
    const int bc = blockIdx.y & 1;
    const int bOff = (NB == 1 || j == 0) ? bOff0 : ((j == 1) ? bOff1 : bOff2);
    float* C = fbuf_ptr((NB == 1 || j == 0) ? c0 : ((j == 1) ? c1 : c2));
    const float* bias = (NB == 1 || j == 0) ? bias0 : ((j == 2) ? bias2 : nullptr);

    __shared__ __half Ahi[128][A_LDM];
    __shared__ __half Alo[128][A_LDM];
    __shared__ __half Bhi[16][B_LDM];
    __shared__ __half Blo[16][B_LDM];
    __shared__ float  sbuf[8][16][20];

    const int tid  = threadIdx.x;
    const int lane = tid & 31;
    const int wid  = tid >> 5;
    const int warp_m = wid & 3;
    const int warp_n = wid >> 2;

    const int br = blockIdx.x;
    const int rowBase = br * 128 + warp_m * 32;
    const int colBase = bc * 128 + warp_n * 64;

    wmma::fragment<wmma::accumulator, 16, 16, 16, float> acc[2][4];
    #pragma unroll
    for (int mt = 0; mt < 2; mt++)
        #pragma unroll
        for (int nt = 0; nt < 4; nt++)
            wmma::fill_fragment(acc[mt][nt], 0.f);

    // A tile 128x16 halves: row tid>>1, 8 k at (tid&1)*8  -> one 16B ld/st each
    const int arow = tid >> 1, acol = (tid & 1) * 8;
    // B tile 16x128 halves: k tid>>4, 8 n at (tid&15)*8
    const int bk = tid >> 4, bn = (tid & 15) * 8;

    const uint4 z16 = make_uint4(0u, 0u, 0u, 0u);

    for (int k0 = 0; k0 < K; k0 += 16) {
        {
            int rg = br * 128 + arow;
            uint4 vh = z16, vl = z16;
            if (rg < Nrows) {
                size_t off = (size_t)rg * K + k0 + acol;
                vh = *(const uint4*)(Ah + off);
                vl = *(const uint4*)(Al + off);
            }
            *(uint4*)&Ahi[arow][acol] = vh;
            *(uint4*)&Alo[arow][acol] = vl;
        }
        {
            size_t off = (size_t)bOff + (size_t)(k0 + bk) * HID + bc * 128 + bn;
            *(uint4*)&Bhi[bk][bn] = *(const uint4*)(g_wh + off);
            *(uint4*)&Blo[bk][bn] = *(const uint4*)(g_wl + off);
        }
        __syncthreads();

        wmma::fragment<wmma::matrix_a, 16, 16, 16, __half, wmma::row_major> a_hi[2], a_lo[2];
        #pragma unroll
        for (int mt = 0; mt < 2; mt++) {
            int mr = warp_m * 32 + mt * 16;
            wmma::load_matrix_sync(a_hi[mt], &Ahi[mr][0], A_LDM);
            wmma::load_matrix_sync(a_lo[mt], &Alo[mr][0], A_LDM);
        }
        #pragma unroll
        for (int nt = 0; nt < 4; nt++) {
            int nc = warp_n * 64 + nt * 16;
            wmma::fragment<wmma::matrix_b, 16, 16, 16, __half, wmma::row_major> b_hi, b_lo;
            wmma::load_matrix_sync(b_hi, &Bhi[0][nc], B_LDM);
            wmma::load_matrix_sync(b_lo, &Blo[0][nc], B_LDM);
            #pragma unroll
            for (int mt = 0; mt < 2; mt++) {
                wmma::mma_sync(acc[mt][nt], a_hi[mt], b_hi, acc[mt][nt]);
                wmma::mma_sync(acc[mt][nt], a_hi[mt], b_lo, acc[mt][nt]);
                wmma::mma_sync(acc[mt][nt], a_lo[mt], b_hi, acc[mt][nt]);
            }
        }
        __syncthreads();
    }

    // ---- epilogue via per-warp staging
    #pragma unroll
    for (int mt = 0; mt < 2; mt++) {
        #pragma unroll
        for (int nt = 0; nt < 4; nt++) {
            wmma::store_matrix_sync(&sbuf[wid][0][0], acc[mt][nt], 20,
                                    wmma::mem_row_major);
            __syncwarp();
            int r = lane >> 1;
            int cb = (lane & 1) * 8;
            int grow = rowBase + mt * 16 + r;
            int gcol = colBase + nt * 16 + cb;
            if (grow < Nrows) {
                float vv[8];
                #pragma unroll
                for (int i = 0; i < 8; i++) {
                    float t = sbuf[wid][r][cb + i];
                    if (bias) t = fmaxf(t + bias[gcol + i], 0.f);
                    vv[i] = t;
                }
                if (WRITEH) {
                    __half hh[8], hl[8];
                    #pragma unroll
                    for (int i = 0; i < 8; i++) {
                        __half hi = __float2half_rn(vv[i]);
                        hh[i] = hi;
                        hl[i] = __float2half_rn(vv[i] - __half2float(hi));
                    }
                    size_t off = (size_t)grow * HID + gcol;
                    *(uint4*)(g_hh + off) = *(const uint4*)hh;
                    *(uint4*)(g_hl + off) = *(const uint4*)hl;
                } else {
                    float4* cp = (float4*)(C + (size_t)grow * HID + gcol);
                    cp[0] = make_float4(vv[0], vv[1], vv[2], vv[3]);
                    cp[1] = make_float4(vv[4], vv[5], vv[6], vv[7]);
                }
            }
            __syncwarp();
        }
    }
}

// ---------------- fused GATv2 edge aggregation + bias + skip + LN + relu ----------------
// one warp per node; lane owns channels [lane*8, lane*8+8), head = lane/8
// writes h as hi/lo halves (g_hh/g_hl) for the next GEMM.
__global__ __launch_bounds__(256)
void gat_edge_ln_kernel(const float* __restrict__ att_l,
                        const float* __restrict__ gatb_l,
                        const float* __restrict__ lng_l,
                        const float* __restrict__ lnb_l) {
    const int warp = threadIdx.x >> 5;
    const int lane = threadIdx.x & 31;
    const int i = blockIdx.x * 8 + warp;
    if (i >= NND) return;

    const int head = lane >> 3;
    const int cbase = lane * 8;

    float xr[8], attv[8];
    {
        const float4* p = (const float4*)(g_xr + (size_t)i * HID + cbase);
        float4 a = p[0], b = p[1];
        xr[0]=a.x; xr[1]=a.y; xr[2]=a.z; xr[3]=a.w;
        xr[4]=b.x; xr[5]=b.y; xr[6]=b.z; xr[7]=b.w;
        #pragma unroll
        for (int k = 0; k < 8; k++)
            attv[k] = att_l[head * HEADDIM + (lane & 7) * 8 + k];
    }

    float m = -INFINITY, s = 0.f;
    float accv[8];
    #pragma unroll
    for (int k = 0; k < 8; k++) accv[k] = 0.f;

    const int jb = g_off[i], je = g_off[i + 1];
    for (int j = jb; j < je; j++) {
        const int src = g_csr[j];
        const float4* xp = (const float4*)(g_xl + (size_t)src * HID + cbase);
        float4 a = xp[0], b = xp[1];
        float xlv[8] = {a.x, a.y, a.z, a.w, b.x, b.y, b.z, b.w};

        float partial = 0.f;
        #pragma unroll
        for (int k = 0; k < 8; k++) {
            float t = xlv[k] + xr[k];
            t = (t > 0.f) ? t : 0.2f * t;          // leaky_relu 0.2
            partial = fmaf(t, attv[k], partial);
        }
        partial += __shfl_down_sync(0xffffffffu, partial, 4);
        partial += __shfl_down_sync(0xffffffffu, partial, 2);
        partial += __shfl_down_sync(0xffffffffu, partial, 1);
        const float logit = __shfl_sync(0xffffffffu, partial, lane & ~7);

        const float nm = fmaxf(m, logit);
        const float scale = __expf(m - nm);
        const float p = __expf(logit - nm);
        s = fmaf(s, scale, p);
        m = nm;
        #pragma unroll
        for (int k = 0; k < 8; k++)
            accv[k] = fmaf(accv[k], scale, p * xlv[k]);
    }

    const float inv = 1.f / fmaxf(s, 1e-16f);

    float v[8];
    {
        const float4* sp = (const float4*)(g_skip + (size_t)i * HID + cbase);
        float4 a = sp[0], b = sp[1];
        float sk[8] = {a.x, a.y, a.z, a.w, b.x, b.y, b.z, b.w};
        #pragma unroll
        for (int k = 0; k < 8; k++)
            v[k] = accv[k] * inv + gatb_l[cbase + k] + sk[k];
    }

    float lsum = 0.f;
    #pragma unroll
    for (int k = 0; k < 8; k++) lsum += v[k];
    #pragma unroll
    for (int d = 16; d > 0; d >>= 1) lsum += __shfl_xor_sync(0xffffffffu, lsum, d);
    const float mu = lsum * (1.f / HID);

    float vsum = 0.f;
    #pragma unroll
    for (int k = 0; k < 8; k++) { float ddd = v[k] - mu; vsum = fmaf(ddd, ddd, vsum); }
    #pragma unroll
    for (int d = 16; d > 0; d >>= 1) vsum += __shfl_xor_sync(0xffffffffu, vsum, d);
    const float rstd = rsqrtf(vsum * (1.f / HID) + 1e-5f);

    __half hh[8], hl[8];
    #pragma unroll
    for (int k = 0; k < 8; k++) {
        float t = lng_l[cbase + k] * (v[k] - mu) * rstd + lnb_l[cbase + k];
        t = fmaxf(t, 0.f);
        __half hi = __float2half_rn(t);
        hh[k] = hi;
        hl[k] = __float2half_rn(t - __half2float(hi));
    }
    size_t off = (size_t)i * HID + cbase;
    *(uint4*)(g_hh + off) = *(const uint4*)hh;
    *(uint4*)(g_hl + off) = *(const uint4*)hl;
}

// ---------------- output head: out[i] = dot(tmp[i,:], W2) + b2 ----------------
__global__ __launch_bounds__(256)
void out_head_kernel(const float* __restrict__ W2, const float* __restrict__ b2,
                     float* __restrict__ out) {
    const int warp = threadIdx.x >> 5;
    const int lane = threadIdx.x & 31;
    const int i = blockIdx.x * 8 + warp;
    if (i >= NND) return;

    const float4* tp = (const float4*)(g_tmp + (size_t)i * HID + lane * 8);
    const float4* wp = (const float4*)(W2 + lane * 8);
    float4 t0 = tp[0], t1 = tp[1];
    float4 w0 = wp[0], w1 = wp[1];
    float dsum = t0.x * w0.x + t0.y * w0.y + t0.z * w0.z + t0.w * w0.w
               + t1.x * w1.x + t1.y * w1.y + t1.z * w1.z + t1.w * w1.w;
    #pragma unroll
    for (int d = 16; d > 0; d >>= 1) dsum += __shfl_xor_sync(0xffffffffu, dsum, d);
    if (lane == 0) out[i] = dsum + b2[0];
}

// ---------------- launch ----------------
extern "C" void kernel_launch(void* const* d_in, const int* in_sizes, int n_in,
                              void* d_out, int out_size) {
    const float* x      = (const float*)d_in[0];
    const void*  ei     = d_in[1];                 // int32 OR int64 (device-detected)
    const float* enc_W  = (const float*)d_in[4];
    const float* enc_b  = (const float*)d_in[5];
    const float* Wl     = (const float*)d_in[6];
    const float* Wr     = (const float*)d_in[7];
    const float* att    = (const float*)d_in[8];
    const float* gat_b  = (const float*)d_in[9];
    const float* skip_W = (const float*)d_in[10];
    const float* skip_b = (const float*)d_in[11];
    const float* ln_g   = (const float*)d_in[12];
    const float* ln_b   = (const float*)d_in[13];
    const float* out_W1 = (const float*)d_in[14];
    const float* out_b1 = (const float*)d_in[15];
    const float* out_W2 = (const float*)d_in[16];
    const float* out_b2 = (const float*)d_in[17];
    float* out = (float*)d_out;

    const int NBLK_SCAN = (NND + 511) / 512;

    // CSR build
    detect_kernel<<<1, 32>>>(ei);
    zero_deg_kernel<<<(NND + 511) / 512, 512>>>();
    count_kernel<<<(ETOT + 511) / 512, 512>>>(ei);
    scan1_kernel<<<NBLK_SCAN, 512>>>();
    scan2_kernel<<<1, 32>>>(NBLK_SCAN);
    scan3_kernel<<<NBLK_SCAN, 512>>>();
    fill_kernel<<<(ETOT + 511) / 512, 512>>>(ei);

    // pre-split all GEMM operands into half hi/lo
    split_w_kernel<<<(32768 + 255) / 256, 256>>>(enc_W, WOFF_ENC, 32768);
    split_w_kernel<<<(196608 + 255) / 256, 256>>>(Wl, WOFF_WL, 196608);
    split_w_kernel<<<(196608 + 255) / 256, 256>>>(Wr, WOFF_WR, 196608);
    split_w_kernel<<<(196608 + 255) / 256, 256>>>(skip_W, WOFF_SK, 196608);
    split_w_kernel<<<(65536 + 255) / 256, 256>>>(out_W1, WOFF_OUT, 65536);
    split_x_kernel<<<(NND * INDIM + 255) / 256, 256>>>(x);

    const int NTB = (NND + 127) / 128;            // 196
    const dim3 grid1(NTB, 2);
    const dim3 grid3(NTB, 6);

    // encoder: h = relu(x @ enc_W + enc_b) -> halves
    hgemm_kernel<1, 1><<<grid1, 256>>>(1, WOFF_ENC, 0, 0, enc_b, nullptr,
                                       0, 0, 0, NND, INDIM);

    for (int L = 0; L < NLAYERS; L++) {
        // xl = h@Wl, xr = h@Wr, skip = relu(h@skW + skip_b) — one launch
        hgemm_kernel<3, 0><<<grid3, 256>>>(0, WOFF_WL + L * 65536,
                                           WOFF_WR + L * 65536,
                                           WOFF_SK + L * 65536,
                                           nullptr, skip_b + L * HID,
                                           1, 2, 3, NND, HID);

        gat_edge_ln_kernel<<<(NND + 7) / 8, 256>>>(
            att + L * NHEADS * HEADDIM, gat_b + L * HID,
            ln_g + L * HID, ln_b + L * HID);
    }

    // output head
    hgemm_kernel<1, 0><<<grid1, 256>>>(0, WOFF_OUT, 0, 0, out_b1, nullptr,
                                       4, 4, 4, NND, HID);
    out_head_kernel<<<(NND + 7) / 8, 256>>>(out_W2, out_b2, out);

    (void)in_sizes; (void)n_in; (void)out_size;
}

// round 11
// speedup vs baseline: 2.4196x; 1.0475x over previous
#include <cuda_runtime.h>
#include <mma.h>
#include <cuda_fp16.h>
#include <math.h>
#include <stdint.h>

using namespace nvcuda;

// ---------------- problem constants ----------------
#define NND     25000
#define INDIM   128
#define HID     256
#define NHEADS  4
#define HEADDIM 64
#define NLAYERS 3
#define NE      500000
#define ETOT    (NE + NND)   // reference appends self-loops

// packed weight-split layout (element offsets)
#define WOFF_ENC  0
#define WOFF_WL   32768
#define WOFF_WR   229376
#define WOFF_SK   425984
#define WOFF_OUT  622592
#define WTOT      688128

// ---------------- device scratch (static, no allocation) ----------------
__device__ float  g_xl  [NND * HID];
__device__ float  g_xr  [NND * HID];
__device__ float  g_skip[NND * HID];
__device__ float  g_tmp [NND * HID];
__device__ __half g_hh  [NND * HID];   // h hi-halves
__device__ __half g_hl  [NND * HID];   // h lo-halves
__device__ __half g_exh [NND * INDIM]; // x hi
__device__ __half g_exl [NND * INDIM]; // x lo
__device__ __half g_wh  [WTOT];        // weights hi
__device__ __half g_wl  [WTOT];        // weights lo
__device__ int    g_deg [NND];
__device__ int    g_off [NND + 1];
__device__ int    g_cur [NND];
__device__ int    g_csr [ETOT];
__device__ int    g_incl[NND];
__device__ int    g_bsum[64];
__device__ int    g_is64;

// float scratch ids: 1=xl 2=xr 3=skip 4=tmp
__device__ __forceinline__ float* fbuf_ptr(int id) {
    switch (id) {
        case 1: return g_xl;
        case 2: return g_xr;
        case 3: return g_skip;
        default: return g_tmp;
    }
}

// edge_index declared int64 but JAX x64-disabled silently yields int32.
__global__ void detect_kernel(const void* ei) {
    if (threadIdx.x == 0 && blockIdx.x == 0) {
        const int* w = (const int*)ei;
        int nz = 0;
        #pragma unroll
        for (int k = 0; k < 64; k++) nz |= w[2 * k + 1];
        g_is64 = (nz == 0) ? 1 : 0;
    }
}

__device__ __forceinline__ int load_idx(const void* ei, long long pos) {
    if (g_is64) return (int)((const long long*)ei)[pos];
    return ((const int*)ei)[pos];
}

// ---------------- hi/lo split helpers ----------------
__global__ void split_w_kernel(const float* __restrict__ src, int dstOff, int count) {
    int i = blockIdx.x * blockDim.x + threadIdx.x;
    if (i < count) {
        float v = src[i];
        __half hi = __float2half_rn(v);
        g_wh[dstOff + i] = hi;
        g_wl[dstOff + i] = __float2half_rn(v - __half2float(hi));
    }
}

__global__ void split_x_kernel(const float* __restrict__ src) {
    int i = blockIdx.x * blockDim.x + threadIdx.x;
    if (i < NND * INDIM) {
        float v = src[i];
        __half hi = __float2half_rn(v);
        g_exh[i] = hi;
        g_exl[i] = __float2half_rn(v - __half2float(hi));
    }
}

// ---------------- CSR construction ----------------
__global__ void zero_deg_kernel() {
    int i = blockIdx.x * blockDim.x + threadIdx.x;
    if (i < NND) g_deg[i] = 0;
}

__global__ void count_kernel(const void* __restrict__ ei) {
    int e = blockIdx.x * blockDim.x + threadIdx.x;
    if (e >= ETOT) return;
    int dst = (e < NE) ? load_idx(ei, (long long)NE + e) : (e - NE);
    atomicAdd(&g_deg[dst], 1);
}

__global__ void scan1_kernel() {
    __shared__ int sh[512];
    int idx = blockIdx.x * 512 + threadIdx.x;
    int v = (idx < NND) ? g_deg[idx] : 0;
    sh[threadIdx.x] = v;
    __syncthreads();
    #pragma unroll
    for (int d = 1; d < 512; d <<= 1) {
        int t = (threadIdx.x >= d) ? sh[threadIdx.x - d] : 0;
        __syncthreads();
        sh[threadIdx.x] += t;
        __syncthreads();
    }
    if (idx < NND) g_incl[idx] = sh[threadIdx.x];
    if (threadIdx.x == 511) g_bsum[blockIdx.x] = sh[511];
}

__global__ void scan2_kernel(int nblk) {
    if (threadIdx.x == 0) {
        int run = 0;
        for (int b = 0; b < nblk; b++) {
            int s = g_bsum[b];
            g_bsum[b] = run;
            run += s;
        }
        g_off[NND] = run;
    }
}

__global__ void scan3_kernel() {
    int idx = blockIdx.x * 512 + threadIdx.x;
    if (idx < NND) {
        int e = g_incl[idx] - g_deg[idx] + g_bsum[blockIdx.x];
        g_off[idx] = e;
        g_cur[idx] = e;
    }
}

__global__ void fill_kernel(const void* __restrict__ ei) {
    int e = blockIdx.x * blockDim.x + threadIdx.x;
    if (e >= ETOT) return;
    int src, dst;
    if (e < NE) { src = load_idx(ei, e); dst = load_idx(ei, (long long)NE + e); }
    else        { src = e - NE;          dst = e - NE; }
    int pos = atomicAdd(&g_cur[dst], 1);
    g_csr[pos] = src;
}

// ---------------- 3xFP16-split tensor-core GEMM, double-buffered ----------
// C[N,256] = A[N,K] @ B[K,256], operands pre-split hi/lo.
// D = Ahi*Bhi + Ahi*Blo + Alo*Bhi, fp32 acc. Block 128x128, 8 warps,
// warp tile 32x64 = 2x4 wmma m16n16k16, BK=16, 2-stage smem pipeline
// (one __syncthreads per k-iter). Epilogue sbuf aliases stage memory.

#define A_LDM 24    // halves; 48B row stride
#define B_LDM 136   // halves; 272B row stride
#define ASTAGE_B 12288            // (128*24 halves)*2B per hi/lo pair
#define BSTAGE_B 8704             // (16*136 halves)*2B per hi/lo pair
#define SMEM_TILES (2*ASTAGE_B + 2*BSTAGE_B)   // 41984
#define SBUF_B (8*16*20*4)                     // 10240

template <int NB, int WRITEH>
__global__ __launch_bounds__(256, 2)
void hgemm_kernel(int aId,                       // 0: g_hh/g_hl (K=256), 1: g_exh/g_exl (K=128)
                  int bOff0, int bOff1, int bOff2,
                  const float* __restrict__ bias0, const float* __restrict__ bias2,
                  int c0, int c1, int c2,
                  int Nrows, int K) {
    const __half* Ah = aId ? g_exh : g_hh;
    const __half* Al = aId ? g_exl : g_hl;

    const int j  = blockIdx.y >> 1;
    const int bc = blockIdx.y & 1;
    const int bOff = (NB == 1 || j == 0) ? bOff0 : ((j == 1) ? bOff1 : bOff2);
    float* C = fbuf_ptr((NB == 1 || j == 0) ? c0 : ((j == 1) ? c1 : c2));
    const float* bias = (NB == 1 || j == 0) ? bias0 : ((j == 2) ? bias2 : nullptr);

    __shared__ __align__(16) unsigned char smem_raw[SMEM_TILES];

    const int tid  = threadIdx.x;
    const int lane = tid & 31;
    const int wid  = tid >> 5;
    const int warp_m = wid & 3;
    const int warp_n = wid >> 2;

    const int br = blockIdx.x;
    const int rowBase = br * 128 + warp_m * 32;
    const int colBase = bc * 128 + warp_n * 64;

    wmma::fragment<wmma::accumulator, 16, 16, 16, float> acc[2][4];
    #pragma unroll
    for (int mt = 0; mt < 2; mt++)
        #pragma unroll
        for (int nt = 0; nt < 4; nt++)
            wmma::fill_fragment(acc[mt][nt], 0.f);

    // A tile 128x16 halves: row tid>>1, 8 k at (tid&1)*8
    const int arow = tid >> 1, acol = (tid & 1) * 8;
    // B tile 16x128 halves: k tid>>4, 8 n at (tid&15)*8
    const int bk = tid >> 4, bn = (tid & 15) * 8;

    const int rg = br * 128 + arow;
    const bool aOK = (rg < Nrows);
    const uint4 z16 = make_uint4(0u, 0u, 0u, 0u);
    const int nIter = K >> 4;

    auto AhS = [&](int s) { return (__half*)(smem_raw + s * ASTAGE_B); };
    auto AlS = [&](int s) { return (__half*)(smem_raw + s * ASTAGE_B + ASTAGE_B / 2); };
    auto BhS = [&](int s) { return (__half*)(smem_raw + 2 * ASTAGE_B + s * BSTAGE_B); };
    auto BlS = [&](int s) { return (__half*)(smem_raw + 2 * ASTAGE_B + s * BSTAGE_B + BSTAGE_B / 2); };

    auto ldgTile = [&](int kt, uint4& vAh, uint4& vAl, uint4& vBh, uint4& vBl) {
        int k0 = kt << 4;
        vAh = z16; vAl = z16;
        if (aOK) {
            size_t off = (size_t)rg * K + k0 + acol;
            vAh = *(const uint4*)(Ah + off);
            vAl = *(const uint4*)(Al + off);
        }
        size_t boff = (size_t)bOff + (size_t)(k0 + bk) * HID + bc * 128 + bn;
        vBh = *(const uint4*)(g_wh + boff);
        vBl = *(const uint4*)(g_wl + boff);
    };
    auto stsTile = [&](int s, const uint4& vAh, const uint4& vAl,
                       const uint4& vBh, const uint4& vBl) {
        *(uint4*)(AhS(s) + arow * A_LDM + acol) = vAh;
        *(uint4*)(AlS(s) + arow * A_LDM + acol) = vAl;
        *(uint4*)(BhS(s) + bk * B_LDM + bn) = vBh;
        *(uint4*)(BlS(s) + bk * B_LDM + bn) = vBl;
    };

    // prologue: tile 0 -> stage 0
    uint4 vAh, vAl, vBh, vBl;
    ldgTile(0, vAh, vAl, vBh, vBl);
    stsTile(0, vAh, vAl, vBh, vBl);
    __syncthreads();

    for (int kt = 0; kt < nIter; kt++) {
        const int cur = kt & 1, nxt = cur ^ 1;
        const bool more = (kt + 1 < nIter);
        if (more) ldgTile(kt + 1, vAh, vAl, vBh, vBl);

        wmma::fragment<wmma::matrix_a, 16, 16, 16, __half, wmma::row_major> a_hi[2], a_lo[2];
        #pragma unroll
        for (int mt = 0; mt < 2; mt++) {
            int mr = warp_m * 32 + mt * 16;
            wmma::load_matrix_sync(a_hi[mt], AhS(cur) + mr * A_LDM, A_LDM);
            wmma::load_matrix_sync(a_lo[mt], AlS(cur) + mr * A_LDM, A_LDM);
        }
        #pragma unroll
        for (int nt = 0; nt < 4; nt++) {
            int nc = warp_n * 64 + nt * 16;
            wmma::fragment<wmma::matrix_b, 16, 16, 16, __half, wmma::row_major> b_hi, b_lo;
            wmma::load_matrix_sync(b_hi, BhS(cur) + nc, B_LDM);
            wmma::load_matrix_sync(b_lo, BlS(cur) + nc, B_LDM);
            #pragma unroll
            for (int mt = 0; mt < 2; mt++) {
                wmma::mma_sync(acc[mt][nt], a_hi[mt], b_hi, acc[mt][nt]);
                wmma::mma_sync(acc[mt][nt], a_hi[mt], b_lo, acc[mt][nt]);
                wmma::mma_sync(acc[mt][nt], a_lo[mt], b_hi, acc[mt][nt]);
            }
        }
        if (more) stsTile(nxt, vAh, vAl, vBh, vBl);
        __syncthreads();
    }

    // ---- epilogue: sbuf aliases tile memory (safe after final barrier)
    float* sbuf = (float*)smem_raw + wid * 16 * 20;
    #pragma unroll
    for (int mt = 0; mt < 2; mt++) {
        #pragma unroll
        for (int nt = 0; nt < 4; nt++) {
            wmma::store_matrix_sync(sbuf, acc[mt][nt], 20, wmma::mem_row_major);
            __syncwarp();
            int r = lane >> 1;
            int cb = (lane & 1) * 8;
            int grow = rowBase + mt * 16 + r;
            int gcol = colBase + nt * 16 + cb;
            if (grow < Nrows) {
                float vv[8];
                #pragma unroll
                for (int i = 0; i < 8; i++) {
                    float t = sbuf[r * 20 + cb + i];
                    if (bias) t = fmaxf(t + bias[gcol + i], 0.f);
                    vv[i] = t;
                }
                if (WRITEH) {
                    __half hh[8], hl[8];
                    #pragma unroll
                    for (int i = 0; i < 8; i++) {
                        __half hi = __float2half_rn(vv[i]);
                        hh[i] = hi;
                        hl[i] = __float2half_rn(vv[i] - __half2float(hi));
                    }
                    size_t off = (size_t)grow * HID + gcol;
                    *(uint4*)(g_hh + off) = *(const uint4*)hh;
                    *(uint4*)(g_hl + off) = *(const uint4*)hl;
                } else {
                    float4* cp = (float4*)(C + (size_t)grow * HID + gcol);
                    cp[0] = make_float4(vv[0], vv[1], vv[2], vv[3]);
                    cp[1] = make_float4(vv[4], vv[5], vv[6], vv[7]);
                }
            }
            __syncwarp();
        }
    }
}

// ---------------- fused GATv2 edge aggregation + bias + skip + LN + relu ----------------
// one warp per node; lane owns channels [lane*8, lane*8+8), head = lane/8
// edge loop unrolled x2 (both gathers issued before either reduction).
__global__ __launch_bounds__(256)
void gat_edge_ln_kernel(const float* __restrict__ att_l,
                        const float* __restrict__ gatb_l,
                        const float* __restrict__ lng_l,
                        const float* __restrict__ lnb_l) {
    const int warp = threadIdx.x >> 5;
    const int lane = threadIdx.x & 31;
    const int i = blockIdx.x * 8 + warp;
    if (i >= NND) return;

    const int head = lane >> 3;
    const int cbase = lane * 8;

    float xr[8], attv[8];
    {
        const float4* p = (const float4*)(g_xr + (size_t)i * HID + cbase);
        float4 a = p[0], b = p[1];
        xr[0]=a.x; xr[1]=a.y; xr[2]=a.z; xr[3]=a.w;
        xr[4]=b.x; xr[5]=b.y; xr[6]=b.z; xr[7]=b.w;
        #pragma unroll
        for (int k = 0; k < 8; k++)
            attv[k] = att_l[head * HEADDIM + (lane & 7) * 8 + k];
    }

    float m = -INFINITY, s = 0.f;
    float accv[8];
    #pragma unroll
    for (int k = 0; k < 8; k++) accv[k] = 0.f;

    auto process = [&](const float4& a, const float4& b) {
        float xlv[8] = {a.x, a.y, a.z, a.w, b.x, b.y, b.z, b.w};
        float partial = 0.f;
        #pragma unroll
        for (int k = 0; k < 8; k++) {
            float t = xlv[k] + xr[k];
            t = (t > 0.f) ? t : 0.2f * t;          // leaky_relu 0.2
            partial = fmaf(t, attv[k], partial);
        }
        partial += __shfl_down_sync(0xffffffffu, partial, 4);
        partial += __shfl_down_sync(0xffffffffu, partial, 2);
        partial += __shfl_down_sync(0xffffffffu, partial, 1);
        const float logit = __shfl_sync(0xffffffffu, partial, lane & ~7);

        const float nm = fmaxf(m, logit);
        const float scale = __expf(m - nm);
        const float p = __expf(logit - nm);
        s = fmaf(s, scale, p);
        m = nm;
        #pragma unroll
        for (int k = 0; k < 8; k++)
            accv[k] = fmaf(accv[k], scale, p * xlv[k]);
    };

    const int jb = g_off[i], je = g_off[i + 1];
    int jj = jb;
    for (; jj + 1 < je; jj += 2) {
        const int s0 = g_csr[jj], s1 = g_csr[jj + 1];
        const float4* p0 = (const float4*)(g_xl + (size_t)s0 * HID + cbase);
        const float4* p1 = (const float4*)(g_xl + (size_t)s1 * HID + cbase);
        float4 a0 = p0[0], b0 = p0[1];
        float4 a1 = p1[0], b1 = p1[1];
        process(a0, b0);
        process(a1, b1);
    }
    if (jj < je) {
        const int s0 = g_csr[jj];
        const float4* p0 = (const float4*)(g_xl + (size_t)s0 * HID + cbase);
        float4 a0 = p0[0], b0 = p0[1];
        process(a0, b0);
    }

    const float inv = 1.f / fmaxf(s, 1e-16f);

    float v[8];
    {
        const float4* sp = (const float4*)(g_skip + (size_t)i * HID + cbase);
        float4 a = sp[0], b = sp[1];
        float sk[8] = {a.x, a.y, a.z, a.w, b.x, b.y, b.z, b.w};
        #pragma unroll
        for (int k = 0; k < 8; k++)
            v[k] = accv[k] * inv + gatb_l[cbase + k] + sk[k];
    }

    float lsum = 0.f;
    #pragma unroll
    for (int k = 0; k < 8; k++) lsum += v[k];
    #pragma unroll
    for (int d = 16; d > 0; d >>= 1) lsum += __shfl_xor_sync(0xffffffffu, lsum, d);
    const float mu = lsum * (1.f / HID);

    float vsum = 0.f;
    #pragma unroll
    for (int k = 0; k < 8; k++) { float ddd = v[k] - mu; vsum = fmaf(ddd, ddd, vsum); }
    #pragma unroll
    for (int d = 16; d > 0; d >>= 1) vsum += __shfl_xor_sync(0xffffffffu, vsum, d);
    const float rstd = rsqrtf(vsum * (1.f / HID) + 1e-5f);

    __half hh[8], hl[8];
    #pragma unroll
    for (int k = 0; k < 8; k++) {
        float t = lng_l[cbase + k] * (v[k] - mu) * rstd + lnb_l[cbase + k];
        t = fmaxf(t, 0.f);
        __half hi = __float2half_rn(t);
        hh[k] = hi;
        hl[k] = __float2half_rn(t - __half2float(hi));
    }
    size_t off = (size_t)i * HID + cbase;
    *(uint4*)(g_hh + off) = *(const uint4*)hh;
    *(uint4*)(g_hl + off) = *(const uint4*)hl;
}

// ---------------- output head: out[i] = dot(tmp[i,:], W2) + b2 ----------------
__global__ __launch_bounds__(256)
void out_head_kernel(const float* __restrict__ W2, const float* __restrict__ b2,
                     float* __restrict__ out) {
    const int warp = threadIdx.x >> 5;
    const int lane = threadIdx.x & 31;
    const int i = blockIdx.x * 8 + warp;
    if (i >= NND) return;

    const float4* tp = (const float4*)(g_tmp + (size_t)i * HID + lane * 8);
    const float4* wp = (const float4*)(W2 + lane * 8);
    float4 t0 = tp[0], t1 = tp[1];
    float4 w0 = wp[0], w1 = wp[1];
    float dsum = t0.x * w0.x + t0.y * w0.y + t0.z * w0.z + t0.w * w0.w
               + t1.x * w1.x + t1.y * w1.y + t1.z * w1.z + t1.w * w1.w;
    #pragma unroll
    for (int d = 16; d > 0; d >>= 1) dsum += __shfl_xor_sync(0xffffffffu, dsum, d);
    if (lane == 0) out[i] = dsum + b2[0];
}

// ---------------- launch ----------------
extern "C" void kernel_launch(void* const* d_in, const int* in_sizes, int n_in,
                              void* d_out, int out_size) {
    const float* x      = (const float*)d_in[0];
    const void*  ei     = d_in[1];                 // int32 OR int64 (device-detected)
    const float* enc_W  = (const float*)d_in[4];
    const float* enc_b  = (const float*)d_in[5];
    const float* Wl     = (const float*)d_in[6];
    const float* Wr     = (const float*)d_in[7];
    const float* att    = (const float*)d_in[8];
    const float* gat_b  = (const float*)d_in[9];
    const float* skip_W = (const float*)d_in[10];
    const float* skip_b = (const float*)d_in[11];
    const float* ln_g   = (const float*)d_in[12];
    const float* ln_b   = (const float*)d_in[13];
    const float* out_W1 = (const float*)d_in[14];
    const float* out_b1 = (const float*)d_in[15];
    const float* out_W2 = (const float*)d_in[16];
    const float* out_b2 = (const float*)d_in[17];
    float* out = (float*)d_out;

    const int NBLK_SCAN = (NND + 511) / 512;

    // CSR build
    detect_kernel<<<1, 32>>>(ei);
    zero_deg_kernel<<<(NND + 511) / 512, 512>>>();
    count_kernel<<<(ETOT + 511) / 512, 512>>>(ei);
    scan1_kernel<<<NBLK_SCAN, 512>>>();
    scan2_kernel<<<1, 32>>>(NBLK_SCAN);
    scan3_kernel<<<NBLK_SCAN, 512>>>();
    fill_kernel<<<(ETOT + 511) / 512, 512>>>(ei);

    // pre-split all GEMM operands into half hi/lo
    split_w_kernel<<<(32768 + 255) / 256, 256>>>(enc_W, WOFF_ENC, 32768);
    split_w_kernel<<<(196608 + 255) / 256, 256>>>(Wl, WOFF_WL, 196608);
    split_w_kernel<<<(196608 + 255) / 256, 256>>>(Wr, WOFF_WR, 196608);
    split_w_kernel<<<(196608 + 255) / 256, 256>>>(skip_W, WOFF_SK, 196608);
    split_w_kernel<<<(65536 + 255) / 256, 256>>>(out_W1, WOFF_OUT, 65536);
    split_x_kernel<<<(NND * INDIM + 255) / 256, 256>>>(x);

    const int NTB = (NND + 127) / 128;            // 196
    const dim3 grid1(NTB, 2);
    const dim3 grid3(NTB, 6);

    // encoder: h = relu(x @ enc_W + enc_b) -> halves
    hgemm_kernel<1, 1><<<grid1, 256>>>(1, WOFF_ENC, 0, 0, enc_b, nullptr,
                                       0, 0, 0, NND, INDIM);

    for (int L = 0; L < NLAYERS; L++) {
        // xl = h@Wl, xr = h@Wr, skip = relu(h@skW + skip_b) — one launch
        hgemm_kernel<3, 0><<<grid3, 256>>>(0, WOFF_WL + L * 65536,
                                           WOFF_WR + L * 65536,
                                           WOFF_SK + L * 65536,
                                           nullptr, skip_b + L * HID,
                                           1, 2, 3, NND, HID);

        gat_edge_ln_kernel<<<(NND + 7) / 8, 256>>>(
            att + L * NHEADS * HEADDIM, gat_b + L * HID,
            ln_g + L * HID, ln_b + L * HID);
    }

    // output head
    hgemm_kernel<1, 0><<<grid1, 256>>>(0, WOFF_OUT, 0, 0, out_b1, nullptr,
                                       4, 4, 4, NND, HID);
    out_head_kernel<<<(NND + 7) / 8, 256>>>(out_W2, out_b2, out);

    (void)in_sizes; (void)n_in; (void)out_size;
}

// round 13
// speedup vs baseline: 2.4920x; 1.0299x over previous
#include <cuda_runtime.h>
#include <mma.h>
#include <cuda_fp16.h>
#include <math.h>
#include <stdint.h>

using namespace nvcuda;

// ---------------- problem constants ----------------
#define NND     25000
#define INDIM   128
#define HID     256
#define NHEADS  4
#define HEADDIM 64
#define NLAYERS 3
#define NE      500000
#define ETOT    (NE + NND)   // reference appends self-loops

// packed weight-split layout (element offsets)
#define WOFF_ENC  0
#define WOFF_WL   32768
#define WOFF_WR   229376
#define WOFF_SK   425984
#define WOFF_OUT  622592
#define WTOT      688128

// ---------------- device scratch (static, no allocation) ----------------
__device__ float  g_xl  [NND * HID];
__device__ float  g_xr  [NND * HID];
__device__ float  g_skip[NND * HID];
__device__ float  g_part[NND * 4];     // head partial dots
__device__ __half g_hh  [NND * HID];   // h hi-halves
__device__ __half g_hl  [NND * HID];   // h lo-halves
__device__ __half g_exh [NND * INDIM]; // x hi
__device__ __half g_exl [NND * INDIM]; // x lo
__device__ __half g_wh  [WTOT];        // weights hi
__device__ __half g_wl  [WTOT];        // weights lo
__device__ int    g_deg [NND];
__device__ int    g_off [NND + 1];
__device__ int    g_cur [NND];
__device__ int    g_csr [ETOT];
__device__ int    g_incl[NND];
__device__ int    g_bsum[64];
__device__ int    g_is64;

// float scratch ids: 1=xl 2=xr 3=skip
__device__ __forceinline__ float* fbuf_ptr(int id) {
    switch (id) {
        case 1: return g_xl;
        case 2: return g_xr;
        default: return g_skip;
    }
}

// edge_index declared int64 but JAX x64-disabled silently yields int32.
__global__ void detect_kernel(const void* ei) {
    if (threadIdx.x == 0 && blockIdx.x == 0) {
        const int* w = (const int*)ei;
        int nz = 0;
        #pragma unroll
        for (int k = 0; k < 64; k++) nz |= w[2 * k + 1];
        g_is64 = (nz == 0) ? 1 : 0;
    }
}

__device__ __forceinline__ int load_idx(const void* ei, long long pos) {
    if (g_is64) return (int)((const long long*)ei)[pos];
    return ((const int*)ei)[pos];
}

// ---------------- hi/lo split helpers ----------------
__global__ void split_w_kernel(const float* __restrict__ src, int dstOff, int count) {
    int i = blockIdx.x * blockDim.x + threadIdx.x;
    if (i < count) {
        float v = src[i];
        __half hi = __float2half_rn(v);
        g_wh[dstOff + i] = hi;
        g_wl[dstOff + i] = __float2half_rn(v - __half2float(hi));
    }
}

__global__ void split_x_kernel(const float* __restrict__ src) {
    int i = blockIdx.x * blockDim.x + threadIdx.x;
    if (i < NND * INDIM) {
        float v = src[i];
        __half hi = __float2half_rn(v);
        g_exh[i] = hi;
        g_exl[i] = __float2half_rn(v - __half2float(hi));
    }
}

// ---------------- CSR construction ----------------
__global__ void zero_deg_kernel() {
    int i = blockIdx.x * blockDim.x + threadIdx.x;
    if (i < NND) g_deg[i] = 0;
}

__global__ void count_kernel(const void* __restrict__ ei) {
    int e = blockIdx.x * blockDim.x + threadIdx.x;
    if (e >= ETOT) return;
    int dst = (e < NE) ? load_idx(ei, (long long)NE + e) : (e - NE);
    atomicAdd(&g_deg[dst], 1);
}

__global__ void scan1_kernel() {
    __shared__ int sh[512];
    int idx = blockIdx.x * 512 + threadIdx.x;
    int v = (idx < NND) ? g_deg[idx] : 0;
    sh[threadIdx.x] = v;
    __syncthreads();
    #pragma unroll
    for (int d = 1; d < 512; d <<= 1) {
        int t = (threadIdx.x >= d) ? sh[threadIdx.x - d] : 0;
        __syncthreads();
        sh[threadIdx.x] += t;
        __syncthreads();
    }
    if (idx < NND) g_incl[idx] = sh[threadIdx.x];
    if (threadIdx.x == 511) g_bsum[blockIdx.x] = sh[511];
}

__global__ void scan2_kernel(int nblk) {
    if (threadIdx.x == 0) {
        int run = 0;
        for (int b = 0; b < nblk; b++) {
            int s = g_bsum[b];
            g_bsum[b] = run;
            run += s;
        }
        g_off[NND] = run;
    }
}

__global__ void scan3_kernel() {
    int idx = blockIdx.x * 512 + threadIdx.x;
    if (idx < NND) {
        int e = g_incl[idx] - g_deg[idx] + g_bsum[blockIdx.x];
        g_off[idx] = e;
        g_cur[idx] = e;
    }
}

__global__ void fill_kernel(const void* __restrict__ ei) {
    int e = blockIdx.x * blockDim.x + threadIdx.x;
    if (e >= ETOT) return;
    int src, dst;
    if (e < NE) { src = load_idx(ei, e); dst = load_idx(ei, (long long)NE + e); }
    else        { src = e - NE;          dst = e - NE; }
    int pos = atomicAdd(&g_cur[dst], 1);
    g_csr[pos] = src;
}

// ---------------- cp.async helpers ----------------
__device__ __forceinline__ void cp_async16(unsigned saddr, const void* gptr, bool pred) {
    int sz = pred ? 16 : 0;
    asm volatile("cp.async.cg.shared.global [%0], [%1], 16, %2;\n"
                 :: "r"(saddr), "l"(gptr), "r"(sz));
}
#define CP_COMMIT() asm volatile("cp.async.commit_group;\n" ::: "memory")
#define CP_WAIT0()  asm volatile("cp.async.wait_group 0;\n" ::: "memory")

// ---------------- 3xFP16-split tensor-core GEMM, cp.async double-buffered --
// C[N,256] = A[N,K] @ B[K,256], operands pre-split hi/lo.
// D = Ahi*Bhi + Ahi*Blo + Alo*Bhi, fp32 acc. Block 128x128, 8 warps,
// warp tile 32x64 = 2x4 wmma m16n16k16, BK=16.
// Loop: [wait -> barrier -> cp.async issue k+1 -> compute k].
// MODE: 0 = fp32 C (+bias,relu when bias nonnull)
//       1 = write h hi/lo halves (encoder)
//       2 = fused head: bias+relu then dot with W2 -> g_part
// blockIdx.y: j = y>>1 selects B/C/bias, bc = y&1 selects 128-col half.

#define A_LDM 24    // halves; 48B row stride
#define B_LDM 136   // halves; 272B row stride
#define ASTAGE_B 12288            // (128*24 halves)*2B per hi/lo pair
#define BSTAGE_B 8704             // (16*136 halves)*2B per hi/lo pair
#define SMEM_TILES (2*ASTAGE_B + 2*BSTAGE_B)   // 41984

template <int NB, int MODE>
__global__ __launch_bounds__(256, 2)
void hgemm_kernel(int aId,                       // 0: g_hh/g_hl (K=256), 1: g_exh/g_exl (K=128)
                  int bOff0, int bOff1, int bOff2,
                  const float* __restrict__ bias0, const float* __restrict__ bias2,
                  const float* __restrict__ w2,
                  int c0, int c1, int c2,
                  int Nrows, int K) {
    const __half* Ah = aId ? g_exh : g_hh;
    const __half* Al = aId ? g_exl : g_hl;

    const int j  = blockIdx.y >> 1;
    const int bc = blockIdx.y & 1;
    const int bOff = (NB == 1 || j == 0) ? bOff0 : ((j == 1) ? bOff1 : bOff2);
    float* C = fbuf_ptr((NB == 1 || j == 0) ? c0 : ((j == 1) ? c1 : c2));
    const float* bias = (NB == 1 || j == 0) ? bias0 : ((j == 2) ? bias2 : nullptr);

    __shared__ __align__(16) unsigned char smem_raw[SMEM_TILES];
    const unsigned sbase = (unsigned)__cvta_generic_to_shared(smem_raw);

    const int tid  = threadIdx.x;
    const int lane = tid & 31;
    const int wid  = tid >> 5;
    const int warp_m = wid & 3;
    const int warp_n = wid >> 2;

    const int br = blockIdx.x;
    const int rowBase = br * 128 + warp_m * 32;
    const int colBase = bc * 128 + warp_n * 64;

    wmma::fragment<wmma::accumulator, 16, 16, 16, float> acc[2][4];
    #pragma unroll
    for (int mt = 0; mt < 2; mt++)
        #pragma unroll
        for (int nt = 0; nt < 4; nt++)
            wmma::fill_fragment(acc[mt][nt], 0.f);

    // A tile 128x16 halves: row tid>>1, 8 k at (tid&1)*8
    const int arow = tid >> 1, acol = (tid & 1) * 8;
    // B tile 16x128 halves: k tid>>4, 8 n at (tid&15)*8
    const int bk = tid >> 4, bn = (tid & 15) * 8;

    const int rg = br * 128 + arow;
    const bool aOK = (rg < Nrows);
    const int rgs = aOK ? rg : 0;
    const int nIter = K >> 4;

    const unsigned aslot = (unsigned)(arow * A_LDM + acol) * 2u;
    const unsigned bslot = (unsigned)(bk * B_LDM + bn) * 2u;

    auto issueTile = [&](int kt, int s) {
        int k0 = kt << 4;
        size_t aoff = (size_t)rgs * K + k0 + acol;
        cp_async16(sbase + s * ASTAGE_B + aslot, Ah + aoff, aOK);
        cp_async16(sbase + s * ASTAGE_B + ASTAGE_B / 2 + aslot, Al + aoff, aOK);
        size_t boff = (size_t)bOff + (size_t)(k0 + bk) * HID + bc * 128 + bn;
        cp_async16(sbase + 2 * ASTAGE_B + s * BSTAGE_B + bslot, g_wh + boff, true);
        cp_async16(sbase + 2 * ASTAGE_B + s * BSTAGE_B + BSTAGE_B / 2 + bslot, g_wl + boff, true);
    };
    auto AhS = [&](int s) { return (__half*)(smem_raw + s * ASTAGE_B); };
    auto AlS = [&](int s) { return (__half*)(smem_raw + s * ASTAGE_B + ASTAGE_B / 2); };
    auto BhS = [&](int s) { return (__half*)(smem_raw + 2 * ASTAGE_B + s * BSTAGE_B); };
    auto BlS = [&](int s) { return (__half*)(smem_raw + 2 * ASTAGE_B + s * BSTAGE_B + BSTAGE_B / 2); };

    // prologue: tile 0 -> stage 0
    issueTile(0, 0);
    CP_COMMIT();

    for (int kt = 0; kt < nIter; kt++) {
        const int cur = kt & 1, nxt = cur ^ 1;
        CP_WAIT0();            // tile kt landed
        __syncthreads();       // visible to all; stage nxt free (computed last iter)
        if (kt + 1 < nIter) {
            issueTile(kt + 1, nxt);
            CP_COMMIT();
        }

        wmma::fragment<wmma::matrix_a, 16, 16, 16, __half, wmma::row_major> a_hi[2], a_lo[2];
        #pragma unroll
        for (int mt = 0; mt < 2; mt++) {
            int mr = warp_m * 32 + mt * 16;
            wmma::load_matrix_sync(a_hi[mt], AhS(cur) + mr * A_LDM, A_LDM);
            wmma::load_matrix_sync(a_lo[mt], AlS(cur) + mr * A_LDM, A_LDM);
        }
        #pragma unroll
        for (int nt = 0; nt < 4; nt++) {
            int nc = warp_n * 64 + nt * 16;
            wmma::fragment<wmma::matrix_b, 16, 16, 16, __half, wmma::row_major> b_hi, b_lo;
            wmma::load_matrix_sync(b_hi, BhS(cur) + nc, B_LDM);
            wmma::load_matrix_sync(b_lo, BlS(cur) + nc, B_LDM);
            #pragma unroll
            for (int mt = 0; mt < 2; mt++) {
                wmma::mma_sync(acc[mt][nt], a_hi[mt], b_hi, acc[mt][nt]);
                wmma::mma_sync(acc[mt][nt], a_hi[mt], b_lo, acc[mt][nt]);
                wmma::mma_sync(acc[mt][nt], a_lo[mt], b_hi, acc[mt][nt]);
            }
        }
    }
    __syncthreads();   // all warps done with stage memory before sbuf alias

    // ---- epilogue: sbuf aliases tile memory
    float* sbuf = (float*)smem_raw + wid * 16 * 20;
    #pragma unroll
    for (int mt = 0; mt < 2; mt++) {
        float pdot = 0.f;
        const int r  = lane >> 1;
        const int cb = (lane & 1) * 8;
        const int grow = rowBase + mt * 16 + r;
        #pragma unroll
        for (int nt = 0; nt < 4; nt++) {
            wmma::store_matrix_sync(sbuf, acc[mt][nt], 20, wmma::mem_row_major);
            __syncwarp();
            int gcol = colBase + nt * 16 + cb;
            if (grow < Nrows) {
                float vv[8];
                #pragma unroll
                for (int i = 0; i < 8; i++) {
                    float t = sbuf[r * 20 + cb + i];
                    if (bias) t = fmaxf(t + bias[gcol + i], 0.f);
                    vv[i] = t;
                }
                if (MODE == 2) {
                    #pragma unroll
                    for (int i = 0; i < 8; i++)
                        pdot = fmaf(vv[i], w2[gcol + i], pdot);
                } else if (MODE == 1) {
                    __half hh[8], hl[8];
                    #pragma unroll
                    for (int i = 0; i < 8; i++) {
                        __half hi = __float2half_rn(vv[i]);
                        hh[i] = hi;
                        hl[i] = __float2half_rn(vv[i] - __half2float(hi));
                    }
                    size_t off = (size_t)grow * HID + gcol;
                    *(uint4*)(g_hh + off) = *(const uint4*)hh;
                    *(uint4*)(g_hl + off) = *(const uint4*)hl;
                } else {
                    float4* cp = (float4*)(C + (size_t)grow * HID + gcol);
                    cp[0] = make_float4(vv[0], vv[1], vv[2], vv[3]);
                    cp[1] = make_float4(vv[4], vv[5], vv[6], vv[7]);
                }
            }
            __syncwarp();
        }
        if (MODE == 2) {
            pdot += __shfl_xor_sync(0xffffffffu, pdot, 1);   // merge col halves
            if ((lane & 1) == 0 && grow < Nrows)
                g_part[grow * 4 + bc * 2 + warp_n] = pdot;   // deterministic slot
        }
    }
}

// ---------------- fused GATv2 edge aggregation + bias + skip + LN + relu ----------------
// one warp per node; lane owns channels [lane*8, lane*8+8), head = lane/8
// edge loop unrolled x4 (all gathers issued before any reduction).
__global__ __launch_bounds__(256)
void gat_edge_ln_kernel(const float* __restrict__ att_l,
                        const float* __restrict__ gatb_l,
                        const float* __restrict__ lng_l,
                        const float* __restrict__ lnb_l) {
    const int warp = threadIdx.x >> 5;
    const int lane = threadIdx.x & 31;
    const int i = blockIdx.x * 8 + warp;
    if (i >= NND) return;

    const int head = lane >> 3;
    const int cbase = lane * 8;

    float xr[8], attv[8];
    {
        const float4* p = (const float4*)(g_xr + (size_t)i * HID + cbase);
        float4 a = p[0], b = p[1];
        xr[0]=a.x; xr[1]=a.y; xr[2]=a.z; xr[3]=a.w;
        xr[4]=b.x; xr[5]=b.y; xr[6]=b.z; xr[7]=b.w;
        #pragma unroll
        for (int k = 0; k < 8; k++)
            attv[k] = att_l[head * HEADDIM + (lane & 7) * 8 + k];
    }

    float m = -INFINITY, s = 0.f;
    float accv[8];
    #pragma unroll
    for (int k = 0; k < 8; k++) accv[k] = 0.f;

    auto process = [&](const float4& a, const float4& b) {
        float xlv[8] = {a.x, a.y, a.z, a.w, b.x, b.y, b.z, b.w};
        float partial = 0.f;
        #pragma unroll
        for (int k = 0; k < 8; k++) {
            float t = xlv[k] + xr[k];
            t = (t > 0.f) ? t : 0.2f * t;          // leaky_relu 0.2
            partial = fmaf(t, attv[k], partial);
        }
        partial += __shfl_down_sync(0xffffffffu, partial, 4);
        partial += __shfl_down_sync(0xffffffffu, partial, 2);
        partial += __shfl_down_sync(0xffffffffu, partial, 1);
        const float logit = __shfl_sync(0xffffffffu, partial, lane & ~7);

        const float nm = fmaxf(m, logit);
        const float scale = __expf(m - nm);
        const float p = __expf(logit - nm);
        s = fmaf(s, scale, p);
        m = nm;
        #pragma unroll
        for (int k = 0; k < 8; k++)
            accv[k] = fmaf(accv[k], scale, p * xlv[k]);
    };

    const int jb = g_off[i], je = g_off[i + 1];
    int jj = jb;
    for (; jj + 3 < je; jj += 4) {
        const int s0 = g_csr[jj],     s1 = g_csr[jj + 1];
        const int s2 = g_csr[jj + 2], s3 = g_csr[jj + 3];
        const float4* p0 = (const float4*)(g_xl + (size_t)s0 * HID + cbase);
        const float4* p1 = (const float4*)(g_xl + (size_t)s1 * HID + cbase);
        const float4* p2 = (const float4*)(g_xl + (size_t)s2 * HID + cbase);
        const float4* p3 = (const float4*)(g_xl + (size_t)s3 * HID + cbase);
        float4 a0 = p0[0], b0 = p0[1];
        float4 a1 = p1[0], b1 = p1[1];
        float4 a2 = p2[0], b2 = p2[1];
        float4 a3 = p3[0], b3 = p3[1];
        process(a0, b0);
        process(a1, b1);
        process(a2, b2);
        process(a3, b3);
    }
    for (; jj < je; jj++) {
        const int s0 = g_csr[jj];
        const float4* p0 = (const float4*)(g_xl + (size_t)s0 * HID + cbase);
        float4 a0 = p0[0], b0 = p0[1];
        process(a0, b0);
    }

    const float inv = 1.f / fmaxf(s, 1e-16f);

    float v[8];
    {
        const float4* sp = (const float4*)(g_skip + (size_t)i * HID + cbase);
        float4 a = sp[0], b = sp[1];
        float sk[8] = {a.x, a.y, a.z, a.w, b.x, b.y, b.z, b.w};
        #pragma unroll
        for (int k = 0; k < 8; k++)
            v[k] = accv[k] * inv + gatb_l[cbase + k] + sk[k];
    }

    float lsum = 0.f;
    #pragma unroll
    for (int k = 0; k < 8; k++) lsum += v[k];
    #pragma unroll
    for (int d = 16; d > 0; d >>= 1) lsum += __shfl_xor_sync(0xffffffffu, lsum, d);
    const float mu = lsum * (1.f / HID);

    float vsum = 0.f;
    #pragma unroll
    for (int k = 0; k < 8; k++) { float ddd = v[k] - mu; vsum = fmaf(ddd, ddd, vsum); }
    #pragma unroll
    for (int d = 16; d > 0; d >>= 1) vsum += __shfl_xor_sync(0xffffffffu, vsum, d);
    const float rstd = rsqrtf(vsum * (1.f / HID) + 1e-5f);

    __half hh[8], hl[8];
    #pragma unroll
    for (int k = 0; k < 8; k++) {
        float t = lng_l[cbase + k] * (v[k] - mu) * rstd + lnb_l[cbase + k];
        t = fmaxf(t, 0.f);
        __half hi = __float2half_rn(t);
        hh[k] = hi;
        hl[k] = __float2half_rn(t - __half2float(hi));
    }
    size_t off = (size_t)i * HID + cbase;
    *(uint4*)(g_hh + off) = *(const uint4*)hh;
    *(uint4*)(g_hl + off) = *(const uint4*)hl;
}

// ---------------- head sum: out[i] = sum of 4 partials + b2 ----------------
__global__ __launch_bounds__(256)
void head_sum_kernel(const float* __restrict__ b2, float* __restrict__ out) {
    int i = blockIdx.x * blockDim.x + threadIdx.x;
    if (i < NND) {
        float4 p = *(const float4*)(g_part + i * 4);
        out[i] = p.x + p.y + p.z + p.w + b2[0];
    }
}

// ---------------- launch ----------------
extern "C" void kernel_launch(void* const* d_in, const int* in_sizes, int n_in,
                              void* d_out, int out_size) {
    const float* x      = (const float*)d_in[0];
    const void*  ei     = d_in[1];                 // int32 OR int64 (device-detected)
    const float* enc_W  = (const float*)d_in[4];
    const float* enc_b  = (const float*)d_in[5];
    const float* Wl     = (const float*)d_in[6];
    const float* Wr     = (const float*)d_in[7];
    const float* att    = (const float*)d_in[8];
    const float* gat_b  = (const float*)d_in[9];
    const float* skip_W = (const float*)d_in[10];
    const float* skip_b = (const float*)d_in[11];
    const float* ln_g   = (const float*)d_in[12];
    const float* ln_b   = (const float*)d_in[13];
    const float* out_W1 = (const float*)d_in[14];
    const float* out_b1 = (const float*)d_in[15];
    const float* out_W2 = (const float*)d_in[16];
    const float* out_b2 = (const float*)d_in[17];
    float* out = (float*)d_out;

    const int NBLK_SCAN = (NND + 511) / 512;

    // CSR build
    detect_kernel<<<1, 32>>>(ei);
    zero_deg_kernel<<<(NND + 511) / 512, 512>>>();
    count_kernel<<<(ETOT + 511) / 512, 512>>>(ei);
    scan1_kernel<<<NBLK_SCAN, 512>>>();
    scan2_kernel<<<1, 32>>>(NBLK_SCAN);
    scan3_kernel<<<NBLK_SCAN, 512>>>();
    fill_kernel<<<(ETOT + 511) / 512, 512>>>(ei);

    // pre-split all GEMM operands into half hi/lo
    split_w_kernel<<<(32768 + 255) / 256, 256>>>(enc_W, WOFF_ENC, 32768);
    split_w_kernel<<<(196608 + 255) / 256, 256>>>(Wl, WOFF_WL, 196608);
    split_w_kernel<<<(196608 + 255) / 256, 256>>>(Wr, WOFF_WR, 196608);
    split_w_kernel<<<(196608 + 255) / 256, 256>>>(skip_W, WOFF_SK, 196608);
    split_w_kernel<<<(65536 + 255) / 256, 256>>>(out_W1, WOFF_OUT, 65536);
    split_x_kernel<<<(NND * INDIM + 255) / 256, 256>>>(x);

    const int NTB = (NND + 127) / 128;            // 196
    const dim3 grid1(NTB, 2);
    const dim3 grid3(NTB, 6);

    // encoder: h = relu(x @ enc_W + enc_b) -> halves
    hgemm_kernel<1, 1><<<grid1, 256>>>(1, WOFF_ENC, 0, 0, enc_b, nullptr, nullptr,
                                       0, 0, 0, NND, INDIM);

    for (int L = 0; L < NLAYERS; L++) {
        // xl = h@Wl, xr = h@Wr, skip = relu(h@skW + skip_b) — one launch
        hgemm_kernel<3, 0><<<grid3, 256>>>(0, WOFF_WL + L * 65536,
                                           WOFF_WR + L * 65536,
                                           WOFF_SK + L * 65536,
                                           nullptr, skip_b + L * HID, nullptr,
                                           1, 2, 3, NND, HID);

        gat_edge_ln_kernel<<<(NND + 7) / 8, 256>>>(
            att + L * NHEADS * HEADDIM, gat_b + L * HID,
            ln_g + L * HID, ln_b + L * HID);
    }

    // fused output head: partial dots in GEMM epilogue, then tiny sum
    hgemm_kernel<1, 2><<<grid1, 256>>>(0, WOFF_OUT, 0, 0, out_b1, nullptr, out_W2,
                                       1, 1, 1, NND, HID);
    head_sum_kernel<<<(NND + 255) / 256, 256>>>(out_b2, out);

    (void)in_sizes; (void)n_in; (void)out_size;
}

// round 14
// speedup vs baseline: 2.5660x; 1.0297x over previous
#include <cuda_runtime.h>
#include <mma.h>
#include <cuda_fp16.h>
#include <math.h>
#include <stdint.h>

using namespace nvcuda;

// ---------------- problem constants ----------------
#define NND     25000
#define INDIM   128
#define HID     256
#define NHEADS  4
#define HEADDIM 64
#define NLAYERS 3
#define NE      500000
#define ETOT    (NE + NND)   // reference appends self-loops

// packed weight-split layout (element offsets)
#define WOFF_ENC  0
#define WOFF_WL   32768
#define WOFF_WR   229376
#define WOFF_SK   425984
#define WOFF_OUT  622592
#define WTOT      688128

// ---------------- device scratch (static, no allocation) ----------------
__device__ float  g_xl  [NND * HID];
__device__ float  g_xr  [NND * HID];
__device__ float  g_skip[NND * HID];
__device__ float  g_part[NND * 4];     // head partial dots
__device__ __half g_hh  [NND * HID];   // h hi-halves
__device__ __half g_hl  [NND * HID];   // h lo-halves
__device__ __half g_exh [NND * INDIM]; // x hi
__device__ __half g_exl [NND * INDIM]; // x lo
__device__ __half g_wh  [WTOT];        // weights hi
__device__ __half g_wl  [WTOT];        // weights lo
__device__ int    g_deg [NND];
__device__ int    g_off [NND + 1];
__device__ int    g_cur [NND];
__device__ int    g_csr [ETOT];
__device__ int    g_incl[NND];
__device__ int    g_bsum[64];
__device__ int    g_is64;

// float scratch ids: 1=xl 2=xr 3=skip
__device__ __forceinline__ float* fbuf_ptr(int id) {
    switch (id) {
        case 1: return g_xl;
        case 2: return g_xr;
        default: return g_skip;
    }
}

__device__ __forceinline__ int load_idx(const void* ei, long long pos) {
    if (g_is64) return (int)((const long long*)ei)[pos];
    return ((const int*)ei)[pos];
}

// ---------------- hi/lo split helpers ----------------
// single launch splitting all 5 weight matrices (range dispatch)
__global__ void split_all_kernel(const float* __restrict__ encW,
                                 const float* __restrict__ Wl,
                                 const float* __restrict__ Wr,
                                 const float* __restrict__ skW,
                                 const float* __restrict__ outW) {
    int i = blockIdx.x * blockDim.x + threadIdx.x;
    if (i >= WTOT) return;
    const float* src; int local;
    if (i < WOFF_WL)       { src = encW; local = i - WOFF_ENC; }
    else if (i < WOFF_WR)  { src = Wl;   local = i - WOFF_WL; }
    else if (i < WOFF_SK)  { src = Wr;   local = i - WOFF_WR; }
    else if (i < WOFF_OUT) { src = skW;  local = i - WOFF_SK; }
    else                   { src = outW; local = i - WOFF_OUT; }
    float v = src[local];
    __half hi = __float2half_rn(v);
    g_wh[i] = hi;
    g_wl[i] = __float2half_rn(v - __half2float(hi));
}

__global__ void split_x_kernel(const float* __restrict__ src) {
    int i = blockIdx.x * blockDim.x + threadIdx.x;
    if (i < NND * INDIM) {
        float v = src[i];
        __half hi = __float2half_rn(v);
        g_exh[i] = hi;
        g_exl[i] = __float2half_rn(v - __half2float(hi));
    }
}

// ---------------- CSR construction ----------------
// zero degrees + dtype-detect (edge_index declared int64, but JAX x64-disabled
// silently yields int32; true int64 <2^31 has all odd 32-bit words zero)
__global__ void zerodetect_kernel(const void* ei) {
    int i = blockIdx.x * blockDim.x + threadIdx.x;
    if (i < NND) g_deg[i] = 0;
    if (blockIdx.x == 0 && threadIdx.x == 0) {
        const int* w = (const int*)ei;
        int nz = 0;
        #pragma unroll
        for (int k = 0; k < 64; k++) nz |= w[2 * k + 1];
        g_is64 = (nz == 0) ? 1 : 0;
    }
}

__global__ void count_kernel(const void* __restrict__ ei) {
    int e = blockIdx.x * blockDim.x + threadIdx.x;
    if (e >= ETOT) return;
    int dst = (e < NE) ? load_idx(ei, (long long)NE + e) : (e - NE);
    atomicAdd(&g_deg[dst], 1);
}

__global__ void scan1_kernel() {
    __shared__ int sh[512];
    int idx = blockIdx.x * 512 + threadIdx.x;
    int v = (idx < NND) ? g_deg[idx] : 0;
    sh[threadIdx.x] = v;
    __syncthreads();
    #pragma unroll
    for (int d = 1; d < 512; d <<= 1) {
        int t = (threadIdx.x >= d) ? sh[threadIdx.x - d] : 0;
        __syncthreads();
        sh[threadIdx.x] += t;
        __syncthreads();
    }
    if (idx < NND) g_incl[idx] = sh[threadIdx.x];
    if (threadIdx.x == 511) g_bsum[blockIdx.x] = sh[511];
}

// parallel exclusive scan of <=64 block sums
__global__ void scan2_kernel(int nblk) {
    __shared__ int sh[64];
    int t = threadIdx.x;
    int v = (t < nblk) ? g_bsum[t] : 0;
    sh[t] = v;
    __syncthreads();
    #pragma unroll
    for (int d = 1; d < 64; d <<= 1) {
        int u = (t >= d) ? sh[t - d] : 0;
        __syncthreads();
        sh[t] += u;
        __syncthreads();
    }
    if (t < nblk) g_bsum[t] = sh[t] - v;     // exclusive
    if (t == nblk - 1) g_off[NND] = sh[t];   // total
}

__global__ void scan3_kernel() {
    int idx = blockIdx.x * 512 + threadIdx.x;
    if (idx < NND) {
        int e = g_incl[idx] - g_deg[idx] + g_bsum[blockIdx.x];
        g_off[idx] = e;
        g_cur[idx] = e;
    }
}

__global__ void fill_kernel(const void* __restrict__ ei) {
    int e = blockIdx.x * blockDim.x + threadIdx.x;
    if (e >= ETOT) return;
    int src, dst;
    if (e < NE) { src = load_idx(ei, e); dst = load_idx(ei, (long long)NE + e); }
    else        { src = e - NE;          dst = e - NE; }
    int pos = atomicAdd(&g_cur[dst], 1);
    g_csr[pos] = src;
}

// ---------------- cp.async helpers ----------------
__device__ __forceinline__ void cp_async16(unsigned saddr, const void* gptr, bool pred) {
    int sz = pred ? 16 : 0;
    asm volatile("cp.async.cg.shared.global [%0], [%1], 16, %2;\n"
                 :: "r"(saddr), "l"(gptr), "r"(sz));
}
#define CP_COMMIT() asm volatile("cp.async.commit_group;\n" ::: "memory")
#define CP_WAIT0()  asm volatile("cp.async.wait_group 0;\n" ::: "memory")

// ---------------- 3xFP16-split tensor-core GEMM, cp.async double-buffered --
// C[N,256] = A[N,K] @ B[K,256], operands pre-split hi/lo.
// D = Ahi*Bhi + Ahi*Blo + Alo*Bhi, fp32 acc. Block 128x128, 8 warps,
// warp tile 32x64 = 2x4 wmma m16n16k16, BK=16.
// Loop: [wait -> barrier -> cp.async issue k+1 -> compute k].
// MODE: 0 = fp32 C (+bias,relu when bias nonnull)
//       1 = write h hi/lo halves (encoder)
//       2 = fused head: bias+relu then dot with W2 -> g_part
// blockIdx.y: j = y>>1 selects B/C/bias, bc = y&1 selects 128-col half.

#define A_LDM 24    // halves; 48B row stride
#define B_LDM 136   // halves; 272B row stride
#define ASTAGE_B 12288            // (128*24 halves)*2B per hi/lo pair
#define BSTAGE_B 8704             // (16*136 halves)*2B per hi/lo pair
#define SMEM_TILES (2*ASTAGE_B + 2*BSTAGE_B)   // 41984

template <int NB, int MODE>
__global__ __launch_bounds__(256, 2)
void hgemm_kernel(int aId,                       // 0: g_hh/g_hl (K=256), 1: g_exh/g_exl (K=128)
                  int bOff0, int bOff1, int bOff2,
                  const float* __restrict__ bias0, const float* __restrict__ bias2,
                  const float* __restrict__ w2,
                  int c0, int c1, int c2,
                  int Nrows, int K) {
    const __half* Ah = aId ? g_exh : g_hh;
    const __half* Al = aId ? g_exl : g_hl;

    const int j  = blockIdx.y >> 1;
    const int bc = blockIdx.y & 1;
    const int bOff = (NB == 1 || j == 0) ? bOff0 : ((j == 1) ? bOff1 : bOff2);
    float* C = fbuf_ptr((NB == 1 || j == 0) ? c0 : ((j == 1) ? c1 : c2));
    const float* bias = (NB == 1 || j == 0) ? bias0 : ((j == 2) ? bias2 : nullptr);

    __shared__ __align__(16) unsigned char smem_raw[SMEM_TILES];
    const unsigned sbase = (unsigned)__cvta_generic_to_shared(smem_raw);

    const int tid  = threadIdx.x;
    const int lane = tid & 31;
    const int wid  = tid >> 5;
    const int warp_m = wid & 3;
    const int warp_n = wid >> 2;

    const int br = blockIdx.x;
    const int rowBase = br * 128 + warp_m * 32;
    const int colBase = bc * 128 + warp_n * 64;

    wmma::fragment<wmma::accumulator, 16, 16, 16, float> acc[2][4];
    #pragma unroll
    for (int mt = 0; mt < 2; mt++)
        #pragma unroll
        for (int nt = 0; nt < 4; nt++)
            wmma::fill_fragment(acc[mt][nt], 0.f);

    // A tile 128x16 halves: row tid>>1, 8 k at (tid&1)*8
    const int arow = tid >> 1, acol = (tid & 1) * 8;
    // B tile 16x128 halves: k tid>>4, 8 n at (tid&15)*8
    const int bk = tid >> 4, bn = (tid & 15) * 8;

    const int rg = br * 128 + arow;
    const bool aOK = (rg < Nrows);
    const int rgs = aOK ? rg : 0;
    const int nIter = K >> 4;

    const unsigned aslot = (unsigned)(arow * A_LDM + acol) * 2u;
    const unsigned bslot = (unsigned)(bk * B_LDM + bn) * 2u;

    auto issueTile = [&](int kt, int s) {
        int k0 = kt << 4;
        size_t aoff = (size_t)rgs * K + k0 + acol;
        cp_async16(sbase + s * ASTAGE_B + aslot, Ah + aoff, aOK);
        cp_async16(sbase + s * ASTAGE_B + ASTAGE_B / 2 + aslot, Al + aoff, aOK);
        size_t boff = (size_t)bOff + (size_t)(k0 + bk) * HID + bc * 128 + bn;
        cp_async16(sbase + 2 * ASTAGE_B + s * BSTAGE_B + bslot, g_wh + boff, true);
        cp_async16(sbase + 2 * ASTAGE_B + s * BSTAGE_B + BSTAGE_B / 2 + bslot, g_wl + boff, true);
    };
    auto AhS = [&](int s) { return (__half*)(smem_raw + s * ASTAGE_B); };
    auto AlS = [&](int s) { return (__half*)(smem_raw + s * ASTAGE_B + ASTAGE_B / 2); };
    auto BhS = [&](int s) { return (__half*)(smem_raw + 2 * ASTAGE_B + s * BSTAGE_B); };
    auto BlS = [&](int s) { return (__half*)(smem_raw + 2 * ASTAGE_B + s * BSTAGE_B + BSTAGE_B / 2); };

    // prologue: tile 0 -> stage 0
    issueTile(0, 0);
    CP_COMMIT();

    for (int kt = 0; kt < nIter; kt++) {
        const int cur = kt & 1, nxt = cur ^ 1;
        CP_WAIT0();            // tile kt landed
        __syncthreads();       // visible to all; stage nxt free (computed last iter)
        if (kt + 1 < nIter) {
            issueTile(kt + 1, nxt);
            CP_COMMIT();
        }

        wmma::fragment<wmma::matrix_a, 16, 16, 16, __half, wmma::row_major> a_hi[2], a_lo[2];
        #pragma unroll
        for (int mt = 0; mt < 2; mt++) {
            int mr = warp_m * 32 + mt * 16;
            wmma::load_matrix_sync(a_hi[mt], AhS(cur) + mr * A_LDM, A_LDM);
            wmma::load_matrix_sync(a_lo[mt], AlS(cur) + mr * A_LDM, A_LDM);
        }
        #pragma unroll
        for (int nt = 0; nt < 4; nt++) {
            int nc = warp_n * 64 + nt * 16;
            wmma::fragment<wmma::matrix_b, 16, 16, 16, __half, wmma::row_major> b_hi, b_lo;
            wmma::load_matrix_sync(b_hi, BhS(cur) + nc, B_LDM);
            wmma::load_matrix_sync(b_lo, BlS(cur) + nc, B_LDM);
            #pragma unroll
            for (int mt = 0; mt < 2; mt++) {
                wmma::mma_sync(acc[mt][nt], a_hi[mt], b_hi, acc[mt][nt]);
                wmma::mma_sync(acc[mt][nt], a_hi[mt], b_lo, acc[mt][nt]);
                wmma::mma_sync(acc[mt][nt], a_lo[mt], b_hi, acc[mt][nt]);
            }
        }
    }
    __syncthreads();   // all warps done with stage memory before sbuf alias

    // ---- epilogue: sbuf aliases tile memory
    float* sbuf = (float*)smem_raw + wid * 16 * 20;
    #pragma unroll
    for (int mt = 0; mt < 2; mt++) {
        float pdot = 0.f;
        const int r  = lane >> 1;
        const int cb = (lane & 1) * 8;
        const int grow = rowBase + mt * 16 + r;
        #pragma unroll
        for (int nt = 0; nt < 4; nt++) {
            wmma::store_matrix_sync(sbuf, acc[mt][nt], 20, wmma::mem_row_major);
            __syncwarp();
            int gcol = colBase + nt * 16 + cb;
            if (grow < Nrows) {
                float vv[8];
                #pragma unroll
                for (int i = 0; i < 8; i++) {
                    float t = sbuf[r * 20 + cb + i];
                    if (bias) t = fmaxf(t + bias[gcol + i], 0.f);
                    vv[i] = t;
                }
                if (MODE == 2) {
                    #pragma unroll
                    for (int i = 0; i < 8; i++)
                        pdot = fmaf(vv[i], w2[gcol + i], pdot);
                } else if (MODE == 1) {
                    __half hh[8], hl[8];
                    #pragma unroll
                    for (int i = 0; i < 8; i++) {
                        __half hi = __float2half_rn(vv[i]);
                        hh[i] = hi;
                        hl[i] = __float2half_rn(vv[i] - __half2float(hi));
                    }
                    size_t off = (size_t)grow * HID + gcol;
                    *(uint4*)(g_hh + off) = *(const uint4*)hh;
                    *(uint4*)(g_hl + off) = *(const uint4*)hl;
                } else {
                    float4* cp = (float4*)(C + (size_t)grow * HID + gcol);
                    cp[0] = make_float4(vv[0], vv[1], vv[2], vv[3]);
                    cp[1] = make_float4(vv[4], vv[5], vv[6], vv[7]);
                }
            }
            __syncwarp();
        }
        if (MODE == 2) {
            pdot += __shfl_xor_sync(0xffffffffu, pdot, 1);   // merge col halves
            if ((lane & 1) == 0 && grow < Nrows)
                g_part[grow * 4 + bc * 2 + warp_n] = pdot;   // deterministic slot
        }
    }
}

// ---------------- fused GATv2 edge aggregation + bias + skip + LN + relu ----------------
// one warp per node; lane owns channels [lane*8, lane*8+8), head = lane/8
// edge loop unrolled x4 (all gathers issued before any reduction).
__global__ __launch_bounds__(256)
void gat_edge_ln_kernel(const float* __restrict__ att_l,
                        const float* __restrict__ gatb_l,
                        const float* __restrict__ lng_l,
                        const float* __restrict__ lnb_l) {
    const int warp = threadIdx.x >> 5;
    const int lane = threadIdx.x & 31;
    const int i = blockIdx.x * 8 + warp;
    if (i >= NND) return;

    const int head = lane >> 3;
    const int cbase = lane * 8;

    float xr[8], attv[8];
    {
        const float4* p = (const float4*)(g_xr + (size_t)i * HID + cbase);
        float4 a = p[0], b = p[1];
        xr[0]=a.x; xr[1]=a.y; xr[2]=a.z; xr[3]=a.w;
        xr[4]=b.x; xr[5]=b.y; xr[6]=b.z; xr[7]=b.w;
        #pragma unroll
        for (int k = 0; k < 8; k++)
            attv[k] = att_l[head * HEADDIM + (lane & 7) * 8 + k];
    }

    float m = -INFINITY, s = 0.f;
    float accv[8];
    #pragma unroll
    for (int k = 0; k < 8; k++) accv[k] = 0.f;

    auto process = [&](const float4& a, const float4& b) {
        float xlv[8] = {a.x, a.y, a.z, a.w, b.x, b.y, b.z, b.w};
        float partial = 0.f;
        #pragma unroll
        for (int k = 0; k < 8; k++) {
            float t = xlv[k] + xr[k];
            t = (t > 0.f) ? t : 0.2f * t;          // leaky_relu 0.2
            partial = fmaf(t, attv[k], partial);
        }
        partial += __shfl_down_sync(0xffffffffu, partial, 4);
        partial += __shfl_down_sync(0xffffffffu, partial, 2);
        partial += __shfl_down_sync(0xffffffffu, partial, 1);
        const float logit = __shfl_sync(0xffffffffu, partial, lane & ~7);

        const float nm = fmaxf(m, logit);
        const float scale = __expf(m - nm);
        const float p = __expf(logit - nm);
        s = fmaf(s, scale, p);
        m = nm;
        #pragma unroll
        for (int k = 0; k < 8; k++)
            accv[k] = fmaf(accv[k], scale, p * xlv[k]);
    };

    const int jb = g_off[i], je = g_off[i + 1];
    int jj = jb;
    for (; jj + 3 < je; jj += 4) {
        const int s0 = g_csr[jj],     s1 = g_csr[jj + 1];
        const int s2 = g_csr[jj + 2], s3 = g_csr[jj + 3];
        const float4* p0 = (const float4*)(g_xl + (size_t)s0 * HID + cbase);
        const float4* p1 = (const float4*)(g_xl + (size_t)s1 * HID + cbase);
        const float4* p2 = (const float4*)(g_xl + (size_t)s2 * HID + cbase);
        const float4* p3 = (const float4*)(g_xl + (size_t)s3 * HID + cbase);
        float4 a0 = p0[0], b0 = p0[1];
        float4 a1 = p1[0], b1 = p1[1];
        float4 a2 = p2[0], b2 = p2[1];
        float4 a3 = p3[0], b3 = p3[1];
        process(a0, b0);
        process(a1, b1);
        process(a2, b2);
        process(a3, b3);
    }
    for (; jj < je; jj++) {
        const int s0 = g_csr[jj];
        const float4* p0 = (const float4*)(g_xl + (size_t)s0 * HID + cbase);
        float4 a0 = p0[0], b0 = p0[1];
        process(a0, b0);
    }

    const float inv = 1.f / fmaxf(s, 1e-16f);

    float v[8];
    {
        const float4* sp = (const float4*)(g_skip + (size_t)i * HID + cbase);
        float4 a = sp[0], b = sp[1];
        float sk[8] = {a.x, a.y, a.z, a.w, b.x, b.y, b.z, b.w};
        #pragma unroll
        for (int k = 0; k < 8; k++)
            v[k] = accv[k] * inv + gatb_l[cbase + k] + sk[k];
    }

    float lsum = 0.f;
    #pragma unroll
    for (int k = 0; k < 8; k++) lsum += v[k];
    #pragma unroll
    for (int d = 16; d > 0; d >>= 1) lsum += __shfl_xor_sync(0xffffffffu, lsum, d);
    const float mu = lsum * (1.f / HID);

    float vsum = 0.f;
    #pragma unroll
    for (int k = 0; k < 8; k++) { float ddd = v[k] - mu; vsum = fmaf(ddd, ddd, vsum); }
    #pragma unroll
    for (int d = 16; d > 0; d >>= 1) vsum += __shfl_xor_sync(0xffffffffu, vsum, d);
    const float rstd = rsqrtf(vsum * (1.f / HID) + 1e-5f);

    __half hh[8], hl[8];
    #pragma unroll
    for (int k = 0; k < 8; k++) {
        float t = lng_l[cbase + k] * (v[k] - mu) * rstd + lnb_l[cbase + k];
        t = fmaxf(t, 0.f);
        __half hi = __float2half_rn(t);
        hh[k] = hi;
        hl[k] = __float2half_rn(t - __half2float(hi));
    }
    size_t off = (size_t)i * HID + cbase;
    *(uint4*)(g_hh + off) = *(const uint4*)hh;
    *(uint4*)(g_hl + off) = *(const uint4*)hl;
}

// ---------------- head sum: out[i] = sum of 4 partials + b2 ----------------
__global__ __launch_bounds__(256)
void head_sum_kernel(const float* __restrict__ b2, float* __restrict__ out) {
    int i = blockIdx.x * blockDim.x + threadIdx.x;
    if (i < NND) {
        float4 p = *(const float4*)(g_part + i * 4);
        out[i] = p.x + p.y + p.z + p.w + b2[0];
    }
}

// ---------------- launch ----------------
extern "C" void kernel_launch(void* const* d_in, const int* in_sizes, int n_in,
                              void* d_out, int out_size) {
    const float* x      = (const float*)d_in[0];
    const void*  ei     = d_in[1];                 // int32 OR int64 (device-detected)
    const float* enc_W  = (const float*)d_in[4];
    const float* enc_b  = (const float*)d_in[5];
    const float* Wl     = (const float*)d_in[6];
    const float* Wr     = (const float*)d_in[7];
    const float* att    = (const float*)d_in[8];
    const float* gat_b  = (const float*)d_in[9];
    const float* skip_W = (const float*)d_in[10];
    const float* skip_b = (const float*)d_in[11];
    const float* ln_g   = (const float*)d_in[12];
    const float* ln_b   = (const float*)d_in[13];
    const float* out_W1 = (const float*)d_in[14];
    const float* out_b1 = (const float*)d_in[15];
    const float* out_W2 = (const float*)d_in[16];
    const float* out_b2 = (const float*)d_in[17];
    float* out = (float*)d_out;

    const int NBLK_SCAN = (NND + 511) / 512;
    const int NTB = (NND + 127) / 128;            // 196
    const dim3 grid1(NTB, 2);
    const dim3 grid3(NTB, 6);

    // Fork a side stream for the CSR build (independent of splits/encoder).
    // kernel_launch is invoked only a few times (correctness + capture), so
    // per-call stream/event creation is fine; no device memory involved.
    cudaStream_t s2;
    cudaStreamCreateWithFlags(&s2, cudaStreamNonBlocking);
    cudaEvent_t evFork, evCsr;
    cudaEventCreateWithFlags(&evFork, cudaEventDisableTiming);
    cudaEventCreateWithFlags(&evCsr, cudaEventDisableTiming);

    cudaEventRecord(evFork, 0);
    cudaStreamWaitEvent(s2, evFork, 0);

    // side stream: CSR build (atomic/latency-bound, low SM occupancy)
    zerodetect_kernel<<<(NND + 511) / 512, 512, 0, s2>>>(ei);
    count_kernel<<<(ETOT + 511) / 512, 512, 0, s2>>>(ei);
    scan1_kernel<<<NBLK_SCAN, 512, 0, s2>>>();
    scan2_kernel<<<1, 64, 0, s2>>>(NBLK_SCAN);
    scan3_kernel<<<NBLK_SCAN, 512, 0, s2>>>();
    fill_kernel<<<(ETOT + 511) / 512, 512, 0, s2>>>(ei);
    cudaEventRecord(evCsr, s2);

    // main stream: splits + encoder + first triple GEMM (tensor/BW-bound)
    split_all_kernel<<<(WTOT + 255) / 256, 256>>>(enc_W, Wl, Wr, skip_W, out_W1);
    split_x_kernel<<<(NND * INDIM + 255) / 256, 256>>>(x);

    // encoder: h = relu(x @ enc_W + enc_b) -> halves
    hgemm_kernel<1, 1><<<grid1, 256>>>(1, WOFF_ENC, 0, 0, enc_b, nullptr, nullptr,
                                       0, 0, 0, NND, INDIM);

    for (int L = 0; L < NLAYERS; L++) {
        // xl = h@Wl, xr = h@Wr, skip = relu(h@skW + skip_b) — one launch
        hgemm_kernel<3, 0><<<grid3, 256>>>(0, WOFF_WL + L * 65536,
                                           WOFF_WR + L * 65536,
                                           WOFF_SK + L * 65536,
                                           nullptr, skip_b + L * HID, nullptr,
                                           1, 2, 3, NND, HID);

        if (L == 0) cudaStreamWaitEvent(0, evCsr, 0);   // join: gat needs CSR

        gat_edge_ln_kernel<<<(NND + 7) / 8, 256>>>(
            att + L * NHEADS * HEADDIM, gat_b + L * HID,
            ln_g + L * HID, ln_b + L * HID);
    }

    // fused output head: partial dots in GEMM epilogue, then tiny sum
    hgemm_kernel<1, 2><<<grid1, 256>>>(0, WOFF_OUT, 0, 0, out_b1, nullptr, out_W2,
                                       1, 1, 1, NND, HID);
    head_sum_kernel<<<(NND + 255) / 256, 256>>>(out_b2, out);

    (void)in_sizes; (void)n_in; (void)out_size;
}